// round 4
// baseline (speedup 1.0000x reference)
#include <cuda_runtime.h>
#include <math.h>

#define BATCH 8
#define SEQ   1315
#define DIMIN 512
#define NOUTC 1536
#define NH    8
#define HD    64
#define NIMG  291
#define NGENE 1024
#define KW    33
#define KPAD  16
#define QK_SCALE 0.125f

// scratch (allocation-free rule: __device__ globals)
__device__ float g_Q[BATCH*NH*SEQ*HD];
__device__ float g_K[BATCH*NH*SEQ*HD];
__device__ float g_V[BATCH*NH*SEQ*HD];

// ---------------------------------------------------------------------------
// Kernel 1: QKV GEMM  X[10520,512] @ W[512,1536] -> scatter into g_Q/g_K/g_V
// 128x128 tile, BK=16, 256 threads, 8x8 per thread.
// ---------------------------------------------------------------------------
__global__ __launch_bounds__(256)
void qkv_gemm_kernel(const float* __restrict__ X, const float* __restrict__ W)
{
    const int M = BATCH * SEQ;
    __shared__ float As[16][128];
    __shared__ float Bs[16][128];
    const int tid = threadIdx.x;
    const int ty = tid >> 4, tx = tid & 15;
    const int row0 = blockIdx.x * 128;
    const int col0 = blockIdx.y * 128;

    float acc[8][8];
#pragma unroll
    for (int a = 0; a < 8; a++)
#pragma unroll
        for (int b = 0; b < 8; b++) acc[a][b] = 0.f;

    for (int k0 = 0; k0 < DIMIN; k0 += 16) {
        // A tile (transposed store)
#pragma unroll
        for (int it = 0; it < 2; it++) {
            int r = (tid >> 2) + it * 64;
            int c = (tid & 3) * 4;
            int gr = row0 + r; if (gr >= M) gr = M - 1;
            float4 a = *(const float4*)(X + gr * DIMIN + k0 + c);
            As[c + 0][r] = a.x; As[c + 1][r] = a.y;
            As[c + 2][r] = a.z; As[c + 3][r] = a.w;
        }
        // B tile (direct)
#pragma unroll
        for (int it = 0; it < 2; it++) {
            int r = (tid >> 5) + it * 8;
            int c = (tid & 31) * 4;
            *(float4*)&Bs[r][c] = *(const float4*)(W + (k0 + r) * NOUTC + col0 + c);
        }
        __syncthreads();
#pragma unroll
        for (int k = 0; k < 16; k++) {
            float ra[8], rb[8];
            *(float4*)(ra)     = *(float4*)&As[k][ty * 8];
            *(float4*)(ra + 4) = *(float4*)&As[k][ty * 8 + 4];
            *(float4*)(rb)     = *(float4*)&Bs[k][tx * 8];
            *(float4*)(rb + 4) = *(float4*)&Bs[k][tx * 8 + 4];
#pragma unroll
            for (int a = 0; a < 8; a++)
#pragma unroll
                for (int b = 0; b < 8; b++) acc[a][b] += ra[a] * rb[b];
        }
        __syncthreads();
    }

    // epilogue scatter: col c -> (q/k/v, head, dd); q scaled
#pragma unroll
    for (int a = 0; a < 8; a++) {
        int m = row0 + ty * 8 + a;
        if (m >= M) continue;
        int bb = m / SEQ, pos = m % SEQ;
#pragma unroll
        for (int b = 0; b < 8; b++) {
            int c = col0 + tx * 8 + b;
            int which = c >> 9;       // 0:q 1:k 2:v
            int hd = c & 511;
            int hh = hd >> 6, dd = hd & 63;
            int idx = ((bb * NH + hh) * SEQ + pos) * HD + dd;
            float v = acc[a][b];
            if (which == 0)      g_Q[idx] = v * QK_SCALE;
            else if (which == 1) g_K[idx] = v;
            else                 g_V[idx] = v;
        }
    }
}

// ---------------------------------------------------------------------------
// Kernel 2: fused attention (flash-style, fp32)
// block = (bh, qtile). BQ=64 queries x BK=64 keys, 256 threads, 4x4/thread.
// key index i (original order) pairs with value v[(i+1024) mod 1315].
// gene queries: single online softmax over all 1315 keys.
// image queries: pass1 stats over gene keys -> inner softmax; pass2 online
//                outer softmax over [p(gene), raw(image)] entries.
// ---------------------------------------------------------------------------
#define PS_STRIDE 68

__device__ __forceinline__ float redmax16(float v) {
    v = fmaxf(v, __shfl_xor_sync(0xffffffffu, v, 8));
    v = fmaxf(v, __shfl_xor_sync(0xffffffffu, v, 4));
    v = fmaxf(v, __shfl_xor_sync(0xffffffffu, v, 2));
    v = fmaxf(v, __shfl_xor_sync(0xffffffffu, v, 1));
    return v;
}
__device__ __forceinline__ float redsum16(float v) {
    v += __shfl_xor_sync(0xffffffffu, v, 8);
    v += __shfl_xor_sync(0xffffffffu, v, 4);
    v += __shfl_xor_sync(0xffffffffu, v, 2);
    v += __shfl_xor_sync(0xffffffffu, v, 1);
    return v;
}

// load 64 key rows (orig index korig0..), transposed: Ks[d*64 + k]
__device__ __forceinline__ void load_kt(const float* __restrict__ Kg, float* Ks,
                                        int korig0, int nk, int tid)
{
    int r = tid >> 4;
    int c4 = (tid & 15) * 4;
#pragma unroll
    for (int it = 0; it < 4; it++) {
        int rr = r + it * 16;
        int kr = korig0 + (rr < nk ? rr : nk - 1);
        float4 kv = *(const float4*)(Kg + kr * HD + c4);
        Ks[(c4 + 0) * 64 + rr] = kv.x; Ks[(c4 + 1) * 64 + rr] = kv.y;
        Ks[(c4 + 2) * 64 + rr] = kv.z; Ks[(c4 + 3) * 64 + rr] = kv.w;
    }
}

// load 64 value rows (v index vbase+r, optional wrap), natural: Vs[k*64 + d]
__device__ __forceinline__ void load_vt(const float* __restrict__ Vg, float* Vs,
                                        int vbase, int nk, bool wrap, int tid)
{
    int r = tid >> 4;
    int c4 = (tid & 15) * 4;
#pragma unroll
    for (int it = 0; it < 4; it++) {
        int rr = r + it * 16;
        int rc = rr < nk ? rr : nk - 1;
        int vidx = vbase + rc;
        if (wrap && vidx >= SEQ) vidx -= SEQ;
        *(float4*)&Vs[rr * 64 + c4] = *(const float4*)(Vg + vidx * HD + c4);
    }
}

__device__ __forceinline__ void compute_s(const float* Qs, const float* Ks,
                                          int ty, int tx, float s[4][4])
{
#pragma unroll
    for (int a = 0; a < 4; a++)
#pragma unroll
        for (int b = 0; b < 4; b++) s[a][b] = 0.f;
#pragma unroll 8
    for (int d = 0; d < 64; d++) {
        float4 q = *(const float4*)&Qs[d * 64 + ty * 4];
        float4 k = *(const float4*)&Ks[d * 64 + tx * 4];
        s[0][0] += q.x * k.x; s[0][1] += q.x * k.y; s[0][2] += q.x * k.z; s[0][3] += q.x * k.w;
        s[1][0] += q.y * k.x; s[1][1] += q.y * k.y; s[1][2] += q.y * k.z; s[1][3] += q.y * k.w;
        s[2][0] += q.z * k.x; s[2][1] += q.z * k.y; s[2][2] += q.z * k.z; s[2][3] += q.z * k.w;
        s[3][0] += q.w * k.x; s[3][1] += q.w * k.y; s[3][2] += q.w * k.z; s[3][3] += q.w * k.w;
    }
}

// online softmax step + P@V accumulation. e entries already masked (-inf).
__device__ __forceinline__ void online_accum(float e[4][4], float m_[4], float l_[4],
                                             float O[4][4], float* Ps,
                                             const float* Vs, int ty, int tx)
{
#pragma unroll
    for (int a = 0; a < 4; a++) {
        float tmax = fmaxf(fmaxf(e[a][0], e[a][1]), fmaxf(e[a][2], e[a][3]));
        tmax = redmax16(tmax);
        float mn = fmaxf(m_[a], tmax);
        float sc = __expf(m_[a] - mn);     // m_=-inf on first tile -> 0
        float rs = 0.f;
#pragma unroll
        for (int b = 0; b < 4; b++) {
            float p = __expf(e[a][b] - mn);
            e[a][b] = p;
            rs += p;
        }
        rs = redsum16(rs);
        l_[a] = l_[a] * sc + rs;
        m_[a] = mn;
#pragma unroll
        for (int b = 0; b < 4; b++) O[a][b] *= sc;
    }
    // write P natural layout (padded stride): Ps[i*68 + j]
#pragma unroll
    for (int a = 0; a < 4; a++) {
        float4 p4;
        p4.x = e[a][0]; p4.y = e[a][1]; p4.z = e[a][2]; p4.w = e[a][3];
        *(float4*)&Ps[(ty * 4 + a) * PS_STRIDE + tx * 4] = p4;
    }
    __syncthreads();
    // O[i][dd] += sum_j P[i][j] * V[j][dd]
#pragma unroll 4
    for (int j = 0; j < 64; j++) {
        float4 v = *(const float4*)&Vs[j * 64 + tx * 4];
        float p0 = Ps[(ty * 4 + 0) * PS_STRIDE + j];
        float p1 = Ps[(ty * 4 + 1) * PS_STRIDE + j];
        float p2 = Ps[(ty * 4 + 2) * PS_STRIDE + j];
        float p3 = Ps[(ty * 4 + 3) * PS_STRIDE + j];
        O[0][0] += p0 * v.x; O[0][1] += p0 * v.y; O[0][2] += p0 * v.z; O[0][3] += p0 * v.w;
        O[1][0] += p1 * v.x; O[1][1] += p1 * v.y; O[1][2] += p1 * v.z; O[1][3] += p1 * v.w;
        O[2][0] += p2 * v.x; O[2][1] += p2 * v.y; O[2][2] += p2 * v.z; O[2][3] += p2 * v.w;
        O[3][0] += p3 * v.x; O[3][1] += p3 * v.y; O[3][2] += p3 * v.z; O[3][3] += p3 * v.w;
    }
}

__global__ __launch_bounds__(256)
void attn_kernel(float* __restrict__ out)
{
    extern __shared__ float sm[];
    float* Qs = sm;                       // [64][64] d-major
    float* Ks = sm + 4096;                // [64][64] d-major
    float* Vs = sm + 8192;                // [64][64] k-major
    float* Ps = sm + 12288;               // [64][68]

    const int bh = blockIdx.x;
    const int qt = blockIdx.y;
    const int tid = threadIdx.x;
    const int ty = tid >> 4, tx = tid & 15;

    const float* __restrict__ Qg = g_Q + bh * SEQ * HD;
    const float* __restrict__ Kg = g_K + bh * SEQ * HD;
    const float* __restrict__ Vg = g_V + bh * SEQ * HD;

    const bool is_img = (qt >= 16);
    int qorig0, tbase, nq;
    if (!is_img) { qorig0 = NIMG + qt * 64; tbase = qt * 64; nq = 64; }
    else {
        int i0 = (qt - 16) * 64;
        qorig0 = i0; tbase = NGENE + i0;
        nq = NIMG - i0; if (nq > 64) nq = 64;
    }

    // load Q tile transposed
    {
        int r = tid >> 4;
        int c4 = (tid & 15) * 4;
#pragma unroll
        for (int it = 0; it < 4; it++) {
            int rr = r + it * 16;
            int qr = qorig0 + (rr < nq ? rr : nq - 1);
            float4 qv = *(const float4*)(Qg + qr * HD + c4);
            Qs[(c4 + 0) * 64 + rr] = qv.x; Qs[(c4 + 1) * 64 + rr] = qv.y;
            Qs[(c4 + 2) * 64 + rr] = qv.z; Qs[(c4 + 3) * 64 + rr] = qv.w;
        }
    }

    float m_[4], l_[4], O[4][4];
#pragma unroll
    for (int a = 0; a < 4; a++) {
        m_[a] = -INFINITY; l_[a] = 0.f;
#pragma unroll
        for (int b = 0; b < 4; b++) O[a][b] = 0.f;
    }

    if (!is_img) {
        // gene queries: plain online softmax over all keys (orig order),
        // value index = (key + 1024) mod 1315
        for (int kt = 0; kt < 21; kt++) {
            int k0 = kt * 64;
            int nk = SEQ - k0; if (nk > 64) nk = 64;
            __syncthreads();
            load_kt(Kg, Ks, k0, nk, tid);
            load_vt(Vg, Vs, k0 + NGENE, nk, true, tid);
            __syncthreads();
            float e[4][4];
            compute_s(Qs, Ks, ty, tx, e);
            if (nk < 64) {
#pragma unroll
                for (int b = 0; b < 4; b++) {
                    if (tx * 4 + b >= nk) {
#pragma unroll
                        for (int a = 0; a < 4; a++) e[a][b] = -INFINITY;
                    }
                }
            }
            online_accum(e, m_, l_, O, Ps, Vs, ty, tx);
        }
    } else {
        // ---- pass 1: inner softmax stats over 1024 gene keys ----
        float mg[4], lg[4];
#pragma unroll
        for (int a = 0; a < 4; a++) { mg[a] = -INFINITY; lg[a] = 0.f; }
        for (int kt = 0; kt < 16; kt++) {
            __syncthreads();
            load_kt(Kg, Ks, NIMG + kt * 64, 64, tid);
            __syncthreads();
            float e[4][4];
            compute_s(Qs, Ks, ty, tx, e);
#pragma unroll
            for (int a = 0; a < 4; a++) {
                float tmax = fmaxf(fmaxf(e[a][0], e[a][1]), fmaxf(e[a][2], e[a][3]));
                tmax = redmax16(tmax);
                float mn = fmaxf(mg[a], tmax);
                float sc = __expf(mg[a] - mn);
                float rs = 0.f;
#pragma unroll
                for (int b = 0; b < 4; b++) rs += __expf(e[a][b] - mn);
                rs = redsum16(rs);
                lg[a] = lg[a] * sc + rs;
                mg[a] = mn;
            }
        }
        float invlg[4];
#pragma unroll
        for (int a = 0; a < 4; a++) invlg[a] = 1.f / lg[a];

        // ---- pass 2a: gene keys, entries = inner softmax probs; v[geneidx] ----
        for (int kt = 0; kt < 16; kt++) {
            __syncthreads();
            load_kt(Kg, Ks, NIMG + kt * 64, 64, tid);
            load_vt(Vg, Vs, kt * 64, 64, false, tid);   // gene key g -> v[g]
            __syncthreads();
            float e[4][4];
            compute_s(Qs, Ks, ty, tx, e);
#pragma unroll
            for (int a = 0; a < 4; a++)
#pragma unroll
                for (int b = 0; b < 4; b++)
                    e[a][b] = __expf(e[a][b] - mg[a]) * invlg[a];
            online_accum(e, m_, l_, O, Ps, Vs, ty, tx);
        }
        // ---- pass 2b: image keys, raw entries; v[key+1024] ----
        for (int kt = 0; kt < 5; kt++) {
            int k0 = kt * 64;
            int nk = NIMG - k0; if (nk > 64) nk = 64;
            __syncthreads();
            load_kt(Kg, Ks, k0, nk, tid);
            load_vt(Vg, Vs, k0 + NGENE, nk, false, tid);
            __syncthreads();
            float e[4][4];
            compute_s(Qs, Ks, ty, tx, e);
            if (nk < 64) {
#pragma unroll
                for (int b = 0; b < 4; b++) {
                    if (tx * 4 + b >= nk) {
#pragma unroll
                        for (int a = 0; a < 4; a++) e[a][b] = -INFINITY;
                    }
                }
            }
            online_accum(e, m_, l_, O, Ps, Vs, ty, tx);
        }
    }

    // epilogue: out[b][t][h*64 + dd]
    const int bb = bh / NH, hh = bh % NH;
#pragma unroll
    for (int a = 0; a < 4; a++) {
        int r = ty * 4 + a;
        if (r >= nq) continue;
        float inv = 1.f / l_[a];
        float4 o;
        o.x = O[a][0] * inv; o.y = O[a][1] * inv;
        o.z = O[a][2] * inv; o.w = O[a][3] * inv;
        int t = tbase + r;
        *(float4*)(out + (bb * SEQ + t) * (NH * HD) + hh * HD + tx * 4) = o;
    }
}

// ---------------------------------------------------------------------------
// Kernel 3: depthwise conv residual over v (original order), added positionally
// ---------------------------------------------------------------------------
__global__ __launch_bounds__(256)
void resid_kernel(const float* __restrict__ wres, float* __restrict__ out)
{
    int idx = blockIdx.x * blockDim.x + threadIdx.x;
    const int total = BATCH * SEQ * NH * HD;
    if (idx >= total) return;
    int c = idx & 511;
    int t = (idx >> 9) % SEQ;
    int bb = idx / (SEQ * 512);
    int hh = c >> 6, dd = c & 63;
    const float* __restrict__ v = g_V + ((bb * NH + hh) * SEQ) * HD + dd;
    float s = 0.f;
#pragma unroll
    for (int k = 0; k < KW; k++) {
        int p = t + k - KPAD;
        if (p >= 0 && p < SEQ) s += wres[hh * KW + k] * v[p * HD];
    }
    out[idx] += s;
}

// ---------------------------------------------------------------------------
extern "C" void kernel_launch(void* const* d_in, const int* in_sizes, int n_in,
                              void* d_out, int out_size)
{
    const float* x     = (const float*)d_in[0];
    const float* w_qkv = (const float*)d_in[1];
    const float* w_res = (const float*)d_in[2];
    float* out = (float*)d_out;

    const int attn_smem = (4096 + 4096 + 4096 + 64 * PS_STRIDE) * 4;  // 66560 B
    cudaFuncSetAttribute(attn_kernel, cudaFuncAttributeMaxDynamicSharedMemorySize, attn_smem);

    dim3 g1((BATCH * SEQ + 127) / 128, NOUTC / 128);
    qkv_gemm_kernel<<<g1, 256>>>(x, w_qkv);

    dim3 g2(BATCH * NH, 21);
    attn_kernel<<<g2, 256, attn_smem>>>(out);

    int total = BATCH * SEQ * NH * HD;
    resid_kernel<<<(total + 255) / 256, 256>>>(w_res, out);
}

// round 5
// speedup vs baseline: 1.0513x; 1.0513x over previous
#include <cuda_runtime.h>
#include <math.h>

#define BATCH 8
#define SEQ   1315
#define DIMIN 512
#define NOUTC 1536
#define NH    8
#define HD    64
#define NIMG  291
#define NGENE 1024
#define KW    33
#define KPAD  16
#define QK_SCALE 0.125f

typedef unsigned long long u64;

// scratch (allocation-free rule: __device__ globals)
__device__ float g_Q[BATCH*NH*SEQ*HD];
__device__ float g_K[BATCH*NH*SEQ*HD];
__device__ float g_V[BATCH*NH*SEQ*HD];

// ---------------------------------------------------------------------------
// packed f32x2 helpers (FFMA2 — 2x fp32 throughput, PTX-only path)
// ---------------------------------------------------------------------------
__device__ __forceinline__ u64 pack2(float x) {
    u64 r; unsigned xi = __float_as_uint(x);
    asm("mov.b64 %0, {%1, %1};" : "=l"(r) : "r"(xi));
    return r;
}
__device__ __forceinline__ void fma2(u64& d, u64 a, u64 b) {
    asm("fma.rn.f32x2 %0, %1, %2, %0;" : "+l"(d) : "l"(a), "l"(b));
}
__device__ __forceinline__ u64 mul2(u64 a, u64 b) {
    u64 d; asm("mul.rn.f32x2 %0, %1, %2;" : "=l"(d) : "l"(a), "l"(b));
    return d;
}
__device__ __forceinline__ float2 unpack2(u64 v) {
    unsigned lo, hi;
    asm("mov.b64 {%0, %1}, %2;" : "=r"(lo), "=r"(hi) : "l"(v));
    return make_float2(__uint_as_float(lo), __uint_as_float(hi));
}

// ---------------------------------------------------------------------------
// Kernel 1: QKV GEMM  X[10520,512] @ W[512,1536] -> scatter into g_Q/g_K/g_V
// 128x128 tile, BK=16, 256 threads, 8x8/thread, FFMA2, double-buffered smem.
// ---------------------------------------------------------------------------
__global__ __launch_bounds__(256)
void qkv_gemm_kernel(const float* __restrict__ X, const float* __restrict__ W)
{
    const int M = BATCH * SEQ;
    __shared__ float As[2][16][128];
    __shared__ float Bs[2][16][128];
    const int tid = threadIdx.x;
    const int ty = tid >> 4, tx = tid & 15;
    const int row0 = blockIdx.x * 128;
    const int col0 = blockIdx.y * 128;

    u64 acc2[8][4];
#pragma unroll
    for (int a = 0; a < 8; a++)
#pragma unroll
        for (int b = 0; b < 4; b++) acc2[a][b] = 0ull;

    // loader lanes
    const int ar = tid >> 2;          // 0..63 (+64)
    const int ac = (tid & 3) * 4;     // 0..12
    const int br = tid >> 5;          // 0..7 (+8)
    const int bc = (tid & 31) * 4;    // 0..124

    float4 pa[2], pb[2];

    // prologue: load k-chunk 0
#pragma unroll
    for (int it = 0; it < 2; it++) {
        int gr = row0 + ar + it * 64; if (gr >= M) gr = M - 1;
        pa[it] = *(const float4*)(X + gr * DIMIN + ac);
        pb[it] = *(const float4*)(W + (br + it * 8) * NOUTC + col0 + bc);
    }
#pragma unroll
    for (int it = 0; it < 2; it++) {
        int r = ar + it * 64;
        As[0][ac + 0][r] = pa[it].x; As[0][ac + 1][r] = pa[it].y;
        As[0][ac + 2][r] = pa[it].z; As[0][ac + 3][r] = pa[it].w;
        *(float4*)&Bs[0][br + it * 8][bc] = pb[it];
    }
    __syncthreads();

    for (int kb = 0; kb < 32; kb++) {
        const int cur = kb & 1, nxt = cur ^ 1;
        const bool more = (kb < 31);
        if (more) {
            int k0 = (kb + 1) * 16;
#pragma unroll
            for (int it = 0; it < 2; it++) {
                int gr = row0 + ar + it * 64; if (gr >= M) gr = M - 1;
                pa[it] = *(const float4*)(X + gr * DIMIN + k0 + ac);
                pb[it] = *(const float4*)(W + (k0 + br + it * 8) * NOUTC + col0 + bc);
            }
        }
#pragma unroll
        for (int k = 0; k < 16; k++) {
            float ra[8];
            *(float4*)(ra)     = *(const float4*)&As[cur][k][ty * 8];
            *(float4*)(ra + 4) = *(const float4*)&As[cur][k][ty * 8 + 4];
            ulonglong2 b0 = *(const ulonglong2*)&Bs[cur][k][tx * 8];
            ulonglong2 b1 = *(const ulonglong2*)&Bs[cur][k][tx * 8 + 4];
#pragma unroll
            for (int a = 0; a < 8; a++) {
                u64 aa = pack2(ra[a]);
                fma2(acc2[a][0], aa, b0.x);
                fma2(acc2[a][1], aa, b0.y);
                fma2(acc2[a][2], aa, b1.x);
                fma2(acc2[a][3], aa, b1.y);
            }
        }
        if (more) {
#pragma unroll
            for (int it = 0; it < 2; it++) {
                int r = ar + it * 64;
                As[nxt][ac + 0][r] = pa[it].x; As[nxt][ac + 1][r] = pa[it].y;
                As[nxt][ac + 2][r] = pa[it].z; As[nxt][ac + 3][r] = pa[it].w;
                *(float4*)&Bs[nxt][br + it * 8][bc] = pb[it];
            }
        }
        __syncthreads();
    }

    // epilogue scatter: col block of 4 stays within one (which, head) -> float4 stores
#pragma unroll
    for (int a = 0; a < 8; a++) {
        int m = row0 + ty * 8 + a;
        if (m >= M) continue;
        int bb = m / SEQ, pos = m % SEQ;
#pragma unroll
        for (int half = 0; half < 2; half++) {
            int c = col0 + tx * 8 + half * 4;
            int which = c >> 9;          // 0:q 1:k 2:v
            int hd = c & 511;
            int hh = hd >> 6, dd = hd & 63;
            int idx = ((bb * NH + hh) * SEQ + pos) * HD + dd;
            float2 x0 = unpack2(acc2[a][half * 2]);
            float2 x1 = unpack2(acc2[a][half * 2 + 1]);
            float4 o;
            if (which == 0) {
                o.x = x0.x * QK_SCALE; o.y = x0.y * QK_SCALE;
                o.z = x1.x * QK_SCALE; o.w = x1.y * QK_SCALE;
                *(float4*)(g_Q + idx) = o;
            } else {
                o.x = x0.x; o.y = x0.y; o.z = x1.x; o.w = x1.y;
                if (which == 1) *(float4*)(g_K + idx) = o;
                else            *(float4*)(g_V + idx) = o;
            }
        }
    }
}

// ---------------------------------------------------------------------------
// Kernel 2: fused attention (flash-style, fp32, FFMA2, double-buffered K/V)
// ---------------------------------------------------------------------------
#define PS_STRIDE 68

__device__ __forceinline__ float redmax16(float v) {
    v = fmaxf(v, __shfl_xor_sync(0xffffffffu, v, 8));
    v = fmaxf(v, __shfl_xor_sync(0xffffffffu, v, 4));
    v = fmaxf(v, __shfl_xor_sync(0xffffffffu, v, 2));
    v = fmaxf(v, __shfl_xor_sync(0xffffffffu, v, 1));
    return v;
}
__device__ __forceinline__ float redsum16(float v) {
    v += __shfl_xor_sync(0xffffffffu, v, 8);
    v += __shfl_xor_sync(0xffffffffu, v, 4);
    v += __shfl_xor_sync(0xffffffffu, v, 2);
    v += __shfl_xor_sync(0xffffffffu, v, 1);
    return v;
}

struct TileD { int kor; int vb; int nk; int mode; bool wrap; };
// mode: 0 = STATS (gene keys, stats only), 1 = GENEP (inner-softmax probs), 2 = RAW

__device__ __forceinline__ TileD tdesc(bool is_img, int t) {
    TileD td;
    if (!is_img) {
        td.kor = t * 64;
        td.nk  = (SEQ - td.kor) < 64 ? (SEQ - td.kor) : 64;
        td.vb  = td.kor + NGENE;
        td.mode = 2; td.wrap = true;
    } else if (t < 16) {
        td.kor = NIMG + t * 64; td.nk = 64; td.vb = -1; td.mode = 0; td.wrap = false;
    } else if (t < 32) {
        td.kor = NIMG + (t - 16) * 64; td.nk = 64; td.vb = (t - 16) * 64;
        td.mode = 1; td.wrap = false;
    } else {
        td.kor = (t - 32) * 64;
        td.nk  = (NIMG - td.kor) < 64 ? (NIMG - td.kor) : 64;
        td.vb  = td.kor + NGENE;
        td.mode = 2; td.wrap = false;
    }
    return td;
}

__device__ __forceinline__ void ldg_tile(const float* __restrict__ Kg,
                                         const float* __restrict__ Vg,
                                         const TileD& td, int tid,
                                         float4 kreg[4], float4 vreg[4])
{
    int r = tid >> 4;
    int c4 = (tid & 15) * 4;
#pragma unroll
    for (int it = 0; it < 4; it++) {
        int rr = r + it * 16;
        int rc = rr < td.nk ? rr : td.nk - 1;
        kreg[it] = *(const float4*)(Kg + (td.kor + rc) * HD + c4);
        if (td.vb >= 0) {
            int vi = td.vb + rc;
            if (td.wrap && vi >= SEQ) vi -= SEQ;
            vreg[it] = *(const float4*)(Vg + vi * HD + c4);
        }
    }
}

__device__ __forceinline__ void sts_tile(float* Ks, float* Vs, const TileD& td,
                                         int tid, const float4 kreg[4],
                                         const float4 vreg[4])
{
    int r = tid >> 4;
    int c4 = (tid & 15) * 4;
#pragma unroll
    for (int it = 0; it < 4; it++) {
        int rr = r + it * 16;
        Ks[(c4 + 0) * 64 + rr] = kreg[it].x; Ks[(c4 + 1) * 64 + rr] = kreg[it].y;
        Ks[(c4 + 2) * 64 + rr] = kreg[it].z; Ks[(c4 + 3) * 64 + rr] = kreg[it].w;
        if (td.vb >= 0)
            *(float4*)&Vs[rr * 64 + c4] = vreg[it];
    }
}

__device__ __forceinline__ void compute_s2(const float* Qs, const float* Ks,
                                           int ty, int tx, float e[4][4])
{
    u64 e2[4][2];
#pragma unroll
    for (int a = 0; a < 4; a++) { e2[a][0] = 0ull; e2[a][1] = 0ull; }
#pragma unroll 8
    for (int d = 0; d < 64; d++) {
        float4 q = *(const float4*)&Qs[d * 64 + ty * 4];
        ulonglong2 kp = *(const ulonglong2*)&Ks[d * 64 + tx * 4];
        u64 q0 = pack2(q.x), q1 = pack2(q.y), q2 = pack2(q.z), q3 = pack2(q.w);
        fma2(e2[0][0], q0, kp.x); fma2(e2[0][1], q0, kp.y);
        fma2(e2[1][0], q1, kp.x); fma2(e2[1][1], q1, kp.y);
        fma2(e2[2][0], q2, kp.x); fma2(e2[2][1], q2, kp.y);
        fma2(e2[3][0], q3, kp.x); fma2(e2[3][1], q3, kp.y);
    }
#pragma unroll
    for (int a = 0; a < 4; a++) {
        float2 f0 = unpack2(e2[a][0]);
        float2 f1 = unpack2(e2[a][1]);
        e[a][0] = f0.x; e[a][1] = f0.y; e[a][2] = f1.x; e[a][3] = f1.y;
    }
}

__global__ __launch_bounds__(256)
void attn_kernel(float* __restrict__ out)
{
    extern __shared__ float sm[];
    float* Qs   = sm;                    // [64][64] d-major
    float* Ksb[2] = { sm + 4096,  sm + 8192  };
    float* Vsb[2] = { sm + 12288, sm + 16384 };
    float* Ps   = sm + 20480;            // [64][68]

    const int bh = blockIdx.x;
    const int qt = blockIdx.y;
    const int tid = threadIdx.x;
    const int ty = tid >> 4, tx = tid & 15;

    const float* __restrict__ Qg = g_Q + bh * SEQ * HD;
    const float* __restrict__ Kg = g_K + bh * SEQ * HD;
    const float* __restrict__ Vg = g_V + bh * SEQ * HD;

    const bool is_img = (qt >= 16);
    int qorig0, tbase, nq;
    if (!is_img) { qorig0 = NIMG + qt * 64; tbase = qt * 64; nq = 64; }
    else {
        int i0 = (qt - 16) * 64;
        qorig0 = i0; tbase = NGENE + i0;
        nq = NIMG - i0; if (nq > 64) nq = 64;
    }

    // load Q tile transposed
    {
        int r = tid >> 4;
        int c4 = (tid & 15) * 4;
#pragma unroll
        for (int it = 0; it < 4; it++) {
            int rr = r + it * 16;
            int qr = qorig0 + (rr < nq ? rr : nq - 1);
            float4 qv = *(const float4*)(Qg + qr * HD + c4);
            Qs[(c4 + 0) * 64 + rr] = qv.x; Qs[(c4 + 1) * 64 + rr] = qv.y;
            Qs[(c4 + 2) * 64 + rr] = qv.z; Qs[(c4 + 3) * 64 + rr] = qv.w;
        }
    }

    // prologue: tile 0 into buffer 0
    float4 kreg[4], vreg[4];
    {
        TileD td0 = tdesc(is_img, 0);
        ldg_tile(Kg, Vg, td0, tid, kreg, vreg);
        sts_tile(Ksb[0], Vsb[0], td0, tid, kreg, vreg);
    }
    __syncthreads();

    float m_[4], l_[4];
    u64 O2[4][2];
    float mg[4], lg[4], invlg[4];
#pragma unroll
    for (int a = 0; a < 4; a++) {
        m_[a] = -INFINITY; l_[a] = 0.f;
        mg[a] = -INFINITY; lg[a] = 0.f;
        O2[a][0] = 0ull; O2[a][1] = 0ull;
    }

    const int ntiles = is_img ? 37 : 21;

    for (int t = 0; t < ntiles; t++) {
        const int cur = t & 1, nxt = cur ^ 1;
        const bool more = (t + 1 < ntiles);
        TileD td = tdesc(is_img, t);
        TileD tdn;
        if (more) {
            tdn = tdesc(is_img, t + 1);
            ldg_tile(Kg, Vg, tdn, tid, kreg, vreg);
        }

        float e[4][4];
        compute_s2(Qs, Ksb[cur], ty, tx, e);

        if (td.mode == 0) {
            // inner-softmax stats over gene keys
#pragma unroll
            for (int a = 0; a < 4; a++) {
                float tmax = fmaxf(fmaxf(e[a][0], e[a][1]), fmaxf(e[a][2], e[a][3]));
                tmax = redmax16(tmax);
                float mn = fmaxf(mg[a], tmax);
                float sc = __expf(mg[a] - mn);
                float rs = 0.f;
#pragma unroll
                for (int b = 0; b < 4; b++) rs += __expf(e[a][b] - mn);
                rs = redsum16(rs);
                lg[a] = lg[a] * sc + rs;
                mg[a] = mn;
            }
        } else {
            if (is_img && t == 16) {
#pragma unroll
                for (int a = 0; a < 4; a++) invlg[a] = 1.f / lg[a];
            }
            if (td.mode == 1) {
#pragma unroll
                for (int a = 0; a < 4; a++)
#pragma unroll
                    for (int b = 0; b < 4; b++)
                        e[a][b] = __expf(e[a][b] - mg[a]) * invlg[a];
            } else if (td.nk < 64) {
#pragma unroll
                for (int b = 0; b < 4; b++) {
                    if (tx * 4 + b >= td.nk) {
#pragma unroll
                        for (int a = 0; a < 4; a++) e[a][b] = -INFINITY;
                    }
                }
            }
            // online softmax update
#pragma unroll
            for (int a = 0; a < 4; a++) {
                float tmax = fmaxf(fmaxf(e[a][0], e[a][1]), fmaxf(e[a][2], e[a][3]));
                tmax = redmax16(tmax);
                float mn = fmaxf(m_[a], tmax);
                float sc = __expf(m_[a] - mn);
                float rs = 0.f;
#pragma unroll
                for (int b = 0; b < 4; b++) {
                    float p = __expf(e[a][b] - mn);
                    e[a][b] = p; rs += p;
                }
                rs = redsum16(rs);
                l_[a] = l_[a] * sc + rs;
                m_[a] = mn;
                u64 sc2 = pack2(sc);
                O2[a][0] = mul2(O2[a][0], sc2);
                O2[a][1] = mul2(O2[a][1], sc2);
            }
            // write P
#pragma unroll
            for (int a = 0; a < 4; a++) {
                float4 p4; p4.x = e[a][0]; p4.y = e[a][1]; p4.z = e[a][2]; p4.w = e[a][3];
                *(float4*)&Ps[(ty * 4 + a) * PS_STRIDE + tx * 4] = p4;
            }
            __syncthreads();
            // P @ V with FFMA2
            const float* Vs = Vsb[cur];
#pragma unroll 4
            for (int j4 = 0; j4 < 16; j4++) {
                float pr0[4], pr1[4], pr2[4], pr3[4];
                *(float4*)pr0 = *(const float4*)&Ps[(ty * 4 + 0) * PS_STRIDE + j4 * 4];
                *(float4*)pr1 = *(const float4*)&Ps[(ty * 4 + 1) * PS_STRIDE + j4 * 4];
                *(float4*)pr2 = *(const float4*)&Ps[(ty * 4 + 2) * PS_STRIDE + j4 * 4];
                *(float4*)pr3 = *(const float4*)&Ps[(ty * 4 + 3) * PS_STRIDE + j4 * 4];
#pragma unroll
                for (int jj = 0; jj < 4; jj++) {
                    ulonglong2 vp = *(const ulonglong2*)&Vs[(j4 * 4 + jj) * 64 + tx * 4];
                    u64 p0 = pack2(pr0[jj]);
                    u64 p1 = pack2(pr1[jj]);
                    u64 p2 = pack2(pr2[jj]);
                    u64 p3 = pack2(pr3[jj]);
                    fma2(O2[0][0], p0, vp.x); fma2(O2[0][1], p0, vp.y);
                    fma2(O2[1][0], p1, vp.x); fma2(O2[1][1], p1, vp.y);
                    fma2(O2[2][0], p2, vp.x); fma2(O2[2][1], p2, vp.y);
                    fma2(O2[3][0], p3, vp.x); fma2(O2[3][1], p3, vp.y);
                }
            }
        }

        if (more)
            sts_tile(Ksb[nxt], Vsb[nxt], tdn, tid, kreg, vreg);
        __syncthreads();
    }

    // epilogue
    const int bb = bh / NH, hh = bh % NH;
#pragma unroll
    for (int a = 0; a < 4; a++) {
        int r = ty * 4 + a;
        if (r >= nq) continue;
        float inv = 1.f / l_[a];
        float2 o0 = unpack2(O2[a][0]);
        float2 o1 = unpack2(O2[a][1]);
        float4 o;
        o.x = o0.x * inv; o.y = o0.y * inv; o.z = o1.x * inv; o.w = o1.y * inv;
        int t = tbase + r;
        *(float4*)(out + (bb * SEQ + t) * (NH * HD) + hh * HD + tx * 4) = o;
    }
}

// ---------------------------------------------------------------------------
// Kernel 3: depthwise conv residual over v (original order), register window
// ---------------------------------------------------------------------------
__global__ __launch_bounds__(256)
void resid_kernel(const float* __restrict__ wres, float* __restrict__ out)
{
    const int blk = blockIdx.x;
    const int sb = blk % 21;           // strip group (4 strips of 16)
    const int bh = blk / 21;
    const int bb = bh >> 3, hh = bh & 7;
    const int dd = threadIdx.x & 63;
    const int s = sb * 4 + (threadIdx.x >> 6);
    const int t0 = s * 16;
    if (t0 >= SEQ) return;

    const float* __restrict__ v = g_V + ((bb * NH + hh) * SEQ) * HD + dd;
    const float* __restrict__ w = wres + hh * KW;

    float win[48];
#pragma unroll
    for (int i = 0; i < 48; i++) {
        int p = t0 - KPAD + i;
        win[i] = (p >= 0 && p < SEQ) ? v[p * HD] : 0.f;
    }
    float o[16];
#pragma unroll
    for (int i = 0; i < 16; i++) o[i] = 0.f;
#pragma unroll
    for (int k = 0; k < KW; k++) {
        float wk = __ldg(w + k);
#pragma unroll
        for (int i = 0; i < 16; i++) o[i] += wk * win[i + k];
    }
#pragma unroll
    for (int i = 0; i < 16; i++) {
        int t = t0 + i;
        if (t < SEQ) {
            int oi = (bb * SEQ + t) * (NH * HD) + hh * HD + dd;
            out[oi] += o[i];
        }
    }
}

// ---------------------------------------------------------------------------
extern "C" void kernel_launch(void* const* d_in, const int* in_sizes, int n_in,
                              void* d_out, int out_size)
{
    const float* x     = (const float*)d_in[0];
    const float* w_qkv = (const float*)d_in[1];
    const float* w_res = (const float*)d_in[2];
    float* out = (float*)d_out;

    const int attn_smem = (4096 * 5 + 64 * PS_STRIDE) * 4;   // 99328 B
    cudaFuncSetAttribute(attn_kernel, cudaFuncAttributeMaxDynamicSharedMemorySize, attn_smem);

    dim3 g1((BATCH * SEQ + 127) / 128, NOUTC / 128);
    qkv_gemm_kernel<<<g1, 256>>>(x, w_qkv);

    dim3 g2(BATCH * NH, 21);
    attn_kernel<<<g2, 256, attn_smem>>>(out);

    resid_kernel<<<BATCH * NH * 21, 256>>>(w_res, out);
}

// round 7
// speedup vs baseline: 1.1903x; 1.1322x over previous
#include <cuda_runtime.h>
#include <cuda_bf16.h>
#include <math.h>
#include <stdint.h>

#define BATCH 8
#define SEQ   1315
#define DIMIN 512
#define NOUTC 1536
#define NH    8
#define HD    64
#define NIMG  291
#define NGENE 1024
#define KW    33
#define KPAD  16
#define QK_SCALE 0.125f

typedef unsigned long long u64;

// scratch (allocation-free rule: __device__ globals)
__device__ float g_Q[BATCH*NH*SEQ*HD];
__device__ float g_K[BATCH*NH*SEQ*HD];
__device__ float g_V[BATCH*NH*SEQ*HD];
__device__ __nv_bfloat16 g_Wth[NOUTC*DIMIN];   // [n][k] bf16 hi
__device__ __nv_bfloat16 g_Wtl[NOUTC*DIMIN];   // [n][k] bf16 lo

__device__ __forceinline__ uint32_t smem_u32(const void* p) {
    uint32_t a;
    asm("{ .reg .u64 t; cvta.to.shared.u64 t, %1; cvt.u32.u64 %0, t; }"
        : "=r"(a) : "l"(p));
    return a;
}
__device__ __forceinline__ void bsplit(float x, __nv_bfloat16& h, __nv_bfloat16& l) {
    h = __float2bfloat16(x);
    l = __float2bfloat16(x - __bfloat162float(h));
}
__device__ __forceinline__ unsigned packbf2(__nv_bfloat16 a, __nv_bfloat16 b) {
    __nv_bfloat162 t(a, b);
    return *(unsigned*)&t;
}

// ---------------------------------------------------------------------------
// prep: W[512][1536] f32 -> Wth/Wtl[1536][512] bf16 (transpose + split)
// ---------------------------------------------------------------------------
__global__ void prep_w_kernel(const float* __restrict__ W)
{
    __shared__ float t[32][33];
    const int n0 = blockIdx.x * 32, k0 = blockIdx.y * 32;
    const int tx = threadIdx.x, ty = threadIdx.y;
#pragma unroll
    for (int r = 0; r < 4; r++)
        t[ty + 8 * r][tx] = W[(k0 + ty + 8 * r) * NOUTC + n0 + tx];
    __syncthreads();
#pragma unroll
    for (int r = 0; r < 4; r++) {
        float v = t[tx][ty + 8 * r];
        __nv_bfloat16 h, l;
        bsplit(v, h, l);
        int o = (n0 + ty + 8 * r) * DIMIN + k0 + tx;
        g_Wth[o] = h;
        g_Wtl[o] = l;
    }
}

// ---------------------------------------------------------------------------
// QKV GEMM via mma.sync m16n8k16 bf16x3. CTA 128x128, warp tile 64x32.
// smem (bytes, per stage 40960): Ah[128][40]bf16 | Al | Bh | Bl
// ---------------------------------------------------------------------------
#define AST 40          // bf16 elems per row (80B, conflict-free for ldmatrix)
#define STG 40960

__device__ __forceinline__ void ldmx4(unsigned& r0, unsigned& r1, unsigned& r2,
                                      unsigned& r3, uint32_t addr) {
    asm volatile("ldmatrix.sync.aligned.m8n8.x4.shared.b16 {%0,%1,%2,%3}, [%4];"
                 : "=r"(r0), "=r"(r1), "=r"(r2), "=r"(r3) : "r"(addr));
}
__device__ __forceinline__ void mma16816(float d[4], unsigned a0, unsigned a1,
                                         unsigned a2, unsigned a3,
                                         unsigned b0, unsigned b1) {
    asm volatile(
        "mma.sync.aligned.m16n8k16.row.col.f32.bf16.bf16.f32 "
        "{%0,%1,%2,%3}, {%4,%5,%6,%7}, {%8,%9}, {%0,%1,%2,%3};"
        : "+f"(d[0]), "+f"(d[1]), "+f"(d[2]), "+f"(d[3])
        : "r"(a0), "r"(a1), "r"(a2), "r"(a3), "r"(b0), "r"(b1));
}

__global__ __launch_bounds__(256)
void qkv_gemm_mma(const float* __restrict__ X)
{
    extern __shared__ __align__(16) char smraw[];
    const int tid = threadIdx.x;
    const int wid = tid >> 5, lane = tid & 31;
    const int row0 = blockIdx.x * 128;
    const int col0 = blockIdx.y * 128;
    const int M = BATCH * SEQ;
    const int wm = wid >> 2, wn = wid & 3;
    const int m_base = wm * 64, n_base = wn * 32;

    const uint32_t sbase = smem_u32(smraw);
    // per-lane ldmatrix byte offsets
    const uint32_t aoff = ((m_base + (lane & 15)) * AST + (lane >> 4) * 8) * 2;
    const uint32_t boff = ((n_base + (lane >> 4) * 8 + (lane & 7)) * AST
                           + ((lane >> 3) & 1) * 8) * 2;

    float d[4][4][4];
#pragma unroll
    for (int i = 0; i < 4; i++)
#pragma unroll
        for (int j = 0; j < 4; j++)
#pragma unroll
            for (int c = 0; c < 4; c++) d[i][j][c] = 0.f;

    float4 xa[4]; uint2 wh4[4], wl4[4];

    auto load_chunk = [&](int kc) {
        const int k0 = kc * 32;
#pragma unroll
        for (int it = 0; it < 4; it++) {
            int idx = tid + it * 256;
            int r = idx >> 3, c4 = (idx & 7) * 4;
            int gr = row0 + r; if (gr >= M) gr = M - 1;
            xa[it]  = *(const float4*)(X + gr * DIMIN + k0 + c4);
            wh4[it] = *(const uint2*)(g_Wth + (col0 + r) * DIMIN + k0 + c4);
            wl4[it] = *(const uint2*)(g_Wtl + (col0 + r) * DIMIN + k0 + c4);
        }
    };
    auto store_stage = [&](int s) {
        char* st = smraw + s * STG;
#pragma unroll
        for (int it = 0; it < 4; it++) {
            int idx = tid + it * 256;
            int r = idx >> 3, c4 = (idx & 7) * 4;
            int off = (r * AST + c4) * 2;
            __nv_bfloat16 h0, l0, h1, l1, h2, l2, h3, l3;
            bsplit(xa[it].x, h0, l0); bsplit(xa[it].y, h1, l1);
            bsplit(xa[it].z, h2, l2); bsplit(xa[it].w, h3, l3);
            uint2 ah; ah.x = packbf2(h0, h1); ah.y = packbf2(h2, h3);
            uint2 al; al.x = packbf2(l0, l1); al.y = packbf2(l2, l3);
            *(uint2*)(st + off)             = ah;
            *(uint2*)(st + 10240 + off)     = al;
            *(uint2*)(st + 20480 + off)     = wh4[it];
            *(uint2*)(st + 30720 + off)     = wl4[it];
        }
    };

    load_chunk(0);
    store_stage(0);
    __syncthreads();

    for (int kc = 0; kc < 16; kc++) {
        const int cur = kc & 1;
        const bool more = (kc < 15);
        if (more) load_chunk(kc + 1);

        const uint32_t stg = sbase + cur * STG;
#pragma unroll
        for (int kk = 0; kk < 2; kk++) {
            const uint32_t kkb = kk * 32;          // 16 cols * 2B
            // B fragments (hi & lo), 4 n8-tiles
            unsigned bh[4][2], bl[4][2];
            ldmx4(bh[0][0], bh[0][1], bh[1][0], bh[1][1], stg + 20480 + boff + kkb);
            ldmx4(bh[2][0], bh[2][1], bh[3][0], bh[3][1], stg + 20480 + boff + kkb + 16 * AST * 2);
            ldmx4(bl[0][0], bl[0][1], bl[1][0], bl[1][1], stg + 30720 + boff + kkb);
            ldmx4(bl[2][0], bl[2][1], bl[3][0], bl[3][1], stg + 30720 + boff + kkb + 16 * AST * 2);
#pragma unroll
            for (int mi = 0; mi < 4; mi++) {
                unsigned a0, a1, a2, a3, l0, l1, l2, l3;
                ldmx4(a0, a1, a2, a3, stg + aoff + kkb + mi * 16 * AST * 2);
                ldmx4(l0, l1, l2, l3, stg + 10240 + aoff + kkb + mi * 16 * AST * 2);
#pragma unroll
                for (int ni = 0; ni < 4; ni++) {
                    mma16816(d[mi][ni], a0, a1, a2, a3, bh[ni][0], bh[ni][1]);
                    mma16816(d[mi][ni], a0, a1, a2, a3, bl[ni][0], bl[ni][1]);
                    mma16816(d[mi][ni], l0, l1, l2, l3, bh[ni][0], bh[ni][1]);
                }
            }
        }
        if (more) {
            store_stage(cur ^ 1);
            __syncthreads();
        }
    }

    // epilogue scatter (float2 per row-pair-col-pair)
    const int gid = lane >> 2, tq = lane & 3;
#pragma unroll
    for (int mi = 0; mi < 4; mi++) {
#pragma unroll
        for (int ni = 0; ni < 4; ni++) {
            int gc = col0 + n_base + ni * 8 + tq * 2;
            int which = gc >> 9;
            int hh = (gc >> 6) & 7;
            int dd = gc & 63;
            float sc = (which == 0) ? QK_SCALE : 1.f;
            float* dst = (which == 0 ? g_Q : which == 1 ? g_K : g_V);
#pragma unroll
            for (int hrow = 0; hrow < 2; hrow++) {
                int m = row0 + m_base + mi * 16 + gid + hrow * 8;
                if (m >= M) continue;
                int bb = m / SEQ, pos = m % SEQ;
                float2 o;
                o.x = d[mi][ni][hrow * 2 + 0] * sc;
                o.y = d[mi][ni][hrow * 2 + 1] * sc;
                *(float2*)(dst + ((bb * NH + hh) * SEQ + pos) * HD + dd) = o;
            }
        }
    }
}

// ---------------------------------------------------------------------------
// packed f32x2 helpers + attention (unchanged from R5 passing version)
// ---------------------------------------------------------------------------
__device__ __forceinline__ u64 pack2(float x) {
    u64 r; unsigned xi = __float_as_uint(x);
    asm("mov.b64 %0, {%1, %1};" : "=l"(r) : "r"(xi));
    return r;
}
__device__ __forceinline__ void fma2(u64& d, u64 a, u64 b) {
    asm("fma.rn.f32x2 %0, %1, %2, %0;" : "+l"(d) : "l"(a), "l"(b));
}
__device__ __forceinline__ u64 mul2(u64 a, u64 b) {
    u64 d; asm("mul.rn.f32x2 %0, %1, %2;" : "=l"(d) : "l"(a), "l"(b));
    return d;
}
__device__ __forceinline__ float2 unpack2(u64 v) {
    unsigned lo, hi;
    asm("mov.b64 {%0, %1}, %2;" : "=r"(lo), "=r"(hi) : "l"(v));
    return make_float2(__uint_as_float(lo), __uint_as_float(hi));
}

#define PS_STRIDE 68

__device__ __forceinline__ float redmax16(float v) {
    v = fmaxf(v, __shfl_xor_sync(0xffffffffu, v, 8));
    v = fmaxf(v, __shfl_xor_sync(0xffffffffu, v, 4));
    v = fmaxf(v, __shfl_xor_sync(0xffffffffu, v, 2));
    v = fmaxf(v, __shfl_xor_sync(0xffffffffu, v, 1));
    return v;
}
__device__ __forceinline__ float redsum16(float v) {
    v += __shfl_xor_sync(0xffffffffu, v, 8);
    v += __shfl_xor_sync(0xffffffffu, v, 4);
    v += __shfl_xor_sync(0xffffffffu, v, 2);
    v += __shfl_xor_sync(0xffffffffu, v, 1);
    return v;
}

struct TileD { int kor; int vb; int nk; int mode; bool wrap; };

__device__ __forceinline__ TileD tdesc(bool is_img, int t) {
    TileD td;
    if (!is_img) {
        td.kor = t * 64;
        td.nk  = (SEQ - td.kor) < 64 ? (SEQ - td.kor) : 64;
        td.vb  = td.kor + NGENE;
        td.mode = 2; td.wrap = true;
    } else if (t < 16) {
        td.kor = NIMG + t * 64; td.nk = 64; td.vb = -1; td.mode = 0; td.wrap = false;
    } else if (t < 32) {
        td.kor = NIMG + (t - 16) * 64; td.nk = 64; td.vb = (t - 16) * 64;
        td.mode = 1; td.wrap = false;
    } else {
        td.kor = (t - 32) * 64;
        td.nk  = (NIMG - td.kor) < 64 ? (NIMG - td.kor) : 64;
        td.vb  = td.kor + NGENE;
        td.mode = 2; td.wrap = false;
    }
    return td;
}

__device__ __forceinline__ void ldg_tile(const float* __restrict__ Kg,
                                         const float* __restrict__ Vg,
                                         const TileD& td, int tid,
                                         float4 kreg[4], float4 vreg[4])
{
    int r = tid >> 4;
    int c4 = (tid & 15) * 4;
#pragma unroll
    for (int it = 0; it < 4; it++) {
        int rr = r + it * 16;
        int rc = rr < td.nk ? rr : td.nk - 1;
        kreg[it] = *(const float4*)(Kg + (td.kor + rc) * HD + c4);
        if (td.vb >= 0) {
            int vi = td.vb + rc;
            if (td.wrap && vi >= SEQ) vi -= SEQ;
            vreg[it] = *(const float4*)(Vg + vi * HD + c4);
        }
    }
}

__device__ __forceinline__ void sts_tile(float* Ks, float* Vs, const TileD& td,
                                         int tid, const float4 kreg[4],
                                         const float4 vreg[4])
{
    int r = tid >> 4;
    int c4 = (tid & 15) * 4;
#pragma unroll
    for (int it = 0; it < 4; it++) {
        int rr = r + it * 16;
        Ks[(c4 + 0) * 64 + rr] = kreg[it].x; Ks[(c4 + 1) * 64 + rr] = kreg[it].y;
        Ks[(c4 + 2) * 64 + rr] = kreg[it].z; Ks[(c4 + 3) * 64 + rr] = kreg[it].w;
        if (td.vb >= 0)
            *(float4*)&Vs[rr * 64 + c4] = vreg[it];
    }
}

__device__ __forceinline__ void compute_s2(const float* Qs, const float* Ks,
                                           int ty, int tx, float e[4][4])
{
    u64 e2[4][2];
#pragma unroll
    for (int a = 0; a < 4; a++) { e2[a][0] = 0ull; e2[a][1] = 0ull; }
#pragma unroll 8
    for (int d = 0; d < 64; d++) {
        float4 q = *(const float4*)&Qs[d * 64 + ty * 4];
        ulonglong2 kp = *(const ulonglong2*)&Ks[d * 64 + tx * 4];
        u64 q0 = pack2(q.x), q1 = pack2(q.y), q2 = pack2(q.z), q3 = pack2(q.w);
        fma2(e2[0][0], q0, kp.x); fma2(e2[0][1], q0, kp.y);
        fma2(e2[1][0], q1, kp.x); fma2(e2[1][1], q1, kp.y);
        fma2(e2[2][0], q2, kp.x); fma2(e2[2][1], q2, kp.y);
        fma2(e2[3][0], q3, kp.x); fma2(e2[3][1], q3, kp.y);
    }
#pragma unroll
    for (int a = 0; a < 4; a++) {
        float2 f0 = unpack2(e2[a][0]);
        float2 f1 = unpack2(e2[a][1]);
        e[a][0] = f0.x; e[a][1] = f0.y; e[a][2] = f1.x; e[a][3] = f1.y;
    }
}

__global__ __launch_bounds__(256)
void attn_kernel(float* __restrict__ out)
{
    extern __shared__ float sm[];
    float* Qs   = sm;
    float* Ksb[2] = { sm + 4096,  sm + 8192  };
    float* Vsb[2] = { sm + 12288, sm + 16384 };
    float* Ps   = sm + 20480;

    const int bh = blockIdx.x;
    const int qt = blockIdx.y;
    const int tid = threadIdx.x;
    const int ty = tid >> 4, tx = tid & 15;

    const float* __restrict__ Qg = g_Q + bh * SEQ * HD;
    const float* __restrict__ Kg = g_K + bh * SEQ * HD;
    const float* __restrict__ Vg = g_V + bh * SEQ * HD;

    const bool is_img = (qt >= 16);
    int qorig0, tbase, nq;
    if (!is_img) { qorig0 = NIMG + qt * 64; tbase = qt * 64; nq = 64; }
    else {
        int i0 = (qt - 16) * 64;
        qorig0 = i0; tbase = NGENE + i0;
        nq = NIMG - i0; if (nq > 64) nq = 64;
    }

    {
        int r = tid >> 4;
        int c4 = (tid & 15) * 4;
#pragma unroll
        for (int it = 0; it < 4; it++) {
            int rr = r + it * 16;
            int qr = qorig0 + (rr < nq ? rr : nq - 1);
            float4 qv = *(const float4*)(Qg + qr * HD + c4);
            Qs[(c4 + 0) * 64 + rr] = qv.x; Qs[(c4 + 1) * 64 + rr] = qv.y;
            Qs[(c4 + 2) * 64 + rr] = qv.z; Qs[(c4 + 3) * 64 + rr] = qv.w;
        }
    }

    float4 kreg[4], vreg[4];
    {
        TileD td0 = tdesc(is_img, 0);
        ldg_tile(Kg, Vg, td0, tid, kreg, vreg);
        sts_tile(Ksb[0], Vsb[0], td0, tid, kreg, vreg);
    }
    __syncthreads();

    float m_[4], l_[4];
    u64 O2[4][2];
    float mg[4], lg[4], invlg[4];
#pragma unroll
    for (int a = 0; a < 4; a++) {
        m_[a] = -INFINITY; l_[a] = 0.f;
        mg[a] = -INFINITY; lg[a] = 0.f;
        O2[a][0] = 0ull; O2[a][1] = 0ull;
    }

    const int ntiles = is_img ? 37 : 21;

    for (int t = 0; t < ntiles; t++) {
        const int cur = t & 1, nxt = cur ^ 1;
        const bool more = (t + 1 < ntiles);
        TileD td = tdesc(is_img, t);
        TileD tdn;
        if (more) {
            tdn = tdesc(is_img, t + 1);
            ldg_tile(Kg, Vg, tdn, tid, kreg, vreg);
        }

        float e[4][4];
        compute_s2(Qs, Ksb[cur], ty, tx, e);

        if (td.mode == 0) {
#pragma unroll
            for (int a = 0; a < 4; a++) {
                float tmax = fmaxf(fmaxf(e[a][0], e[a][1]), fmaxf(e[a][2], e[a][3]));
                tmax = redmax16(tmax);
                float mn = fmaxf(mg[a], tmax);
                float sc = __expf(mg[a] - mn);
                float rs = 0.f;
#pragma unroll
                for (int b = 0; b < 4; b++) rs += __expf(e[a][b] - mn);
                rs = redsum16(rs);
                lg[a] = lg[a] * sc + rs;
                mg[a] = mn;
            }
        } else {
            if (is_img && t == 16) {
#pragma unroll
                for (int a = 0; a < 4; a++) invlg[a] = 1.f / lg[a];
            }
            if (td.mode == 1) {
#pragma unroll
                for (int a = 0; a < 4; a++)
#pragma unroll
                    for (int b = 0; b < 4; b++)
                        e[a][b] = __expf(e[a][b] - mg[a]) * invlg[a];
            } else if (td.nk < 64) {
#pragma unroll
                for (int b = 0; b < 4; b++) {
                    if (tx * 4 + b >= td.nk) {
#pragma unroll
                        for (int a = 0; a < 4; a++) e[a][b] = -INFINITY;
                    }
                }
            }
#pragma unroll
            for (int a = 0; a < 4; a++) {
                float tmax = fmaxf(fmaxf(e[a][0], e[a][1]), fmaxf(e[a][2], e[a][3]));
                tmax = redmax16(tmax);
                float mn = fmaxf(m_[a], tmax);
                float sc = __expf(m_[a] - mn);
                float rs = 0.f;
#pragma unroll
                for (int b = 0; b < 4; b++) {
                    float p = __expf(e[a][b] - mn);
                    e[a][b] = p; rs += p;
                }
                rs = redsum16(rs);
                l_[a] = l_[a] * sc + rs;
                m_[a] = mn;
                u64 sc2 = pack2(sc);
                O2[a][0] = mul2(O2[a][0], sc2);
                O2[a][1] = mul2(O2[a][1], sc2);
            }
#pragma unroll
            for (int a = 0; a < 4; a++) {
                float4 p4; p4.x = e[a][0]; p4.y = e[a][1]; p4.z = e[a][2]; p4.w = e[a][3];
                *(float4*)&Ps[(ty * 4 + a) * PS_STRIDE + tx * 4] = p4;
            }
            __syncthreads();
            const float* Vs = Vsb[cur];
#pragma unroll 4
            for (int j4 = 0; j4 < 16; j4++) {
                float pr0[4], pr1[4], pr2[4], pr3[4];
                *(float4*)pr0 = *(const float4*)&Ps[(ty * 4 + 0) * PS_STRIDE + j4 * 4];
                *(float4*)pr1 = *(const float4*)&Ps[(ty * 4 + 1) * PS_STRIDE + j4 * 4];
                *(float4*)pr2 = *(const float4*)&Ps[(ty * 4 + 2) * PS_STRIDE + j4 * 4];
                *(float4*)pr3 = *(const float4*)&Ps[(ty * 4 + 3) * PS_STRIDE + j4 * 4];
#pragma unroll
                for (int jj = 0; jj < 4; jj++) {
                    ulonglong2 vp = *(const ulonglong2*)&Vs[(j4 * 4 + jj) * 64 + tx * 4];
                    u64 p0 = pack2(pr0[jj]);
                    u64 p1 = pack2(pr1[jj]);
                    u64 p2 = pack2(pr2[jj]);
                    u64 p3 = pack2(pr3[jj]);
                    fma2(O2[0][0], p0, vp.x); fma2(O2[0][1], p0, vp.y);
                    fma2(O2[1][0], p1, vp.x); fma2(O2[1][1], p1, vp.y);
                    fma2(O2[2][0], p2, vp.x); fma2(O2[2][1], p2, vp.y);
                    fma2(O2[3][0], p3, vp.x); fma2(O2[3][1], p3, vp.y);
                }
            }
        }

        if (more)
            sts_tile(Ksb[nxt], Vsb[nxt], tdn, tid, kreg, vreg);
        __syncthreads();
    }

    const int bb = bh / NH, hh = bh % NH;
#pragma unroll
    for (int a = 0; a < 4; a++) {
        int r = ty * 4 + a;
        if (r >= nq) continue;
        float inv = 1.f / l_[a];
        float2 o0 = unpack2(O2[a][0]);
        float2 o1 = unpack2(O2[a][1]);
        float4 o;
        o.x = o0.x * inv; o.y = o0.y * inv; o.z = o1.x * inv; o.w = o1.y * inv;
        int t = tbase + r;
        *(float4*)(out + (bb * SEQ + t) * (NH * HD) + hh * HD + tx * 4) = o;
    }
}

// ---------------------------------------------------------------------------
// Kernel 3: depthwise conv residual (unchanged)
// ---------------------------------------------------------------------------
__global__ __launch_bounds__(256)
void resid_kernel(const float* __restrict__ wres, float* __restrict__ out)
{
    const int blk = blockIdx.x;
    const int sb = blk % 21;
    const int bh = blk / 21;
    const int bb = bh >> 3, hh = bh & 7;
    const int dd = threadIdx.x & 63;
    const int s = sb * 4 + (threadIdx.x >> 6);
    const int t0 = s * 16;
    if (t0 >= SEQ) return;

    const float* __restrict__ v = g_V + ((bb * NH + hh) * SEQ) * HD + dd;
    const float* __restrict__ w = wres + hh * KW;

    float win[48];
#pragma unroll
    for (int i = 0; i < 48; i++) {
        int p = t0 - KPAD + i;
        win[i] = (p >= 0 && p < SEQ) ? v[p * HD] : 0.f;
    }
    float o[16];
#pragma unroll
    for (int i = 0; i < 16; i++) o[i] = 0.f;
#pragma unroll
    for (int k = 0; k < KW; k++) {
        float wk = __ldg(w + k);
#pragma unroll
        for (int i = 0; i < 16; i++) o[i] += wk * win[i + k];
    }
#pragma unroll
    for (int i = 0; i < 16; i++) {
        int t = t0 + i;
        if (t < SEQ) {
            int oi = (bb * SEQ + t) * (NH * HD) + hh * HD + dd;
            out[oi] += o[i];
        }
    }
}

// ---------------------------------------------------------------------------
extern "C" void kernel_launch(void* const* d_in, const int* in_sizes, int n_in,
                              void* d_out, int out_size)
{
    const float* x     = (const float*)d_in[0];
    const float* w_qkv = (const float*)d_in[1];
    const float* w_res = (const float*)d_in[2];
    float* out = (float*)d_out;

    const int gemm_smem = 2 * STG;                            // 81920 B
    cudaFuncSetAttribute(qkv_gemm_mma, cudaFuncAttributeMaxDynamicSharedMemorySize, gemm_smem);
    const int attn_smem = (4096 * 5 + 64 * PS_STRIDE) * 4;    // 99328 B
    cudaFuncSetAttribute(attn_kernel, cudaFuncAttributeMaxDynamicSharedMemorySize, attn_smem);

    dim3 gp(NOUTC / 32, DIMIN / 32);
    prep_w_kernel<<<gp, dim3(32, 8)>>>(w_qkv);

    dim3 g1((BATCH * SEQ + 127) / 128, NOUTC / 128);
    qkv_gemm_mma<<<g1, 256, gemm_smem>>>(x);

    dim3 g2(BATCH * NH, 21);
    attn_kernel<<<g2, 256, attn_smem>>>(out);

    resid_kernel<<<BATCH * NH * 21, 256>>>(w_res, out);
}

// round 9
// speedup vs baseline: 2.8835x; 2.4225x over previous
#include <cuda_runtime.h>
#include <cuda_bf16.h>
#include <cuda_fp16.h>
#include <math.h>
#include <stdint.h>

#define BATCH 8
#define SEQ   1315
#define DIMIN 512
#define NOUTC 1536
#define NH    8
#define HD    64
#define NIMG  291
#define NGENE 1024
#define KW    33
#define KPAD  16
#define QK_SCALE 0.125f

// scratch (allocation-free rule: __device__ globals)
__device__ float g_V [BATCH*NH*SEQ*HD];                 // f32 V for resid conv
__device__ __half g_Qh[BATCH*NH*SEQ*HD], g_Ql[BATCH*NH*SEQ*HD];
__device__ __half g_Kh[BATCH*NH*SEQ*HD], g_Kl[BATCH*NH*SEQ*HD];
__device__ __half g_Vh[BATCH*NH*SEQ*HD], g_Vl[BATCH*NH*SEQ*HD];
__device__ __nv_bfloat16 g_Wth[NOUTC*DIMIN];   // [n][k] bf16 hi
__device__ __nv_bfloat16 g_Wtl[NOUTC*DIMIN];   // [n][k] bf16 lo

__device__ __forceinline__ uint32_t smem_u32(const void* p) {
    uint32_t a;
    asm("{ .reg .u64 t; cvta.to.shared.u64 t, %1; cvt.u32.u64 %0, t; }"
        : "=r"(a) : "l"(p));
    return a;
}
__device__ __forceinline__ void bsplit(float x, __nv_bfloat16& h, __nv_bfloat16& l) {
    h = __float2bfloat16(x);
    l = __float2bfloat16(x - __bfloat162float(h));
}
__device__ __forceinline__ unsigned packbf2(__nv_bfloat16 a, __nv_bfloat16 b) {
    __nv_bfloat162 t(a, b);
    return *(unsigned*)&t;
}
__device__ __forceinline__ unsigned packh2(__half a, __half b) {
    __half2 t = __halves2half2(a, b);
    return *(unsigned*)&t;
}

// ---------------------------------------------------------------------------
// prep: W[512][1536] f32 -> Wth/Wtl[1536][512] bf16 (transpose + split)
// ---------------------------------------------------------------------------
__global__ void prep_w_kernel(const float* __restrict__ W)
{
    __shared__ float t[32][33];
    const int n0 = blockIdx.x * 32, k0 = blockIdx.y * 32;
    const int tx = threadIdx.x, ty = threadIdx.y;
#pragma unroll
    for (int r = 0; r < 4; r++)
        t[ty + 8 * r][tx] = W[(k0 + ty + 8 * r) * NOUTC + n0 + tx];
    __syncthreads();
#pragma unroll
    for (int r = 0; r < 4; r++) {
        float v = t[tx][ty + 8 * r];
        __nv_bfloat16 h, l;
        bsplit(v, h, l);
        int o = (n0 + ty + 8 * r) * DIMIN + k0 + tx;
        g_Wth[o] = h;
        g_Wtl[o] = l;
    }
}

// ---------------------------------------------------------------------------
// common MMA helpers
// ---------------------------------------------------------------------------
__device__ __forceinline__ void ldmx4(unsigned& r0, unsigned& r1, unsigned& r2,
                                      unsigned& r3, uint32_t addr) {
    asm volatile("ldmatrix.sync.aligned.m8n8.x4.shared.b16 {%0,%1,%2,%3}, [%4];"
                 : "=r"(r0), "=r"(r1), "=r"(r2), "=r"(r3) : "r"(addr));
}
__device__ __forceinline__ void ldmx4t(unsigned& r0, unsigned& r1, unsigned& r2,
                                       unsigned& r3, uint32_t addr) {
    asm volatile("ldmatrix.sync.aligned.m8n8.x4.trans.shared.b16 {%0,%1,%2,%3}, [%4];"
                 : "=r"(r0), "=r"(r1), "=r"(r2), "=r"(r3) : "r"(addr));
}
__device__ __forceinline__ void mma_bf(float d[4], unsigned a0, unsigned a1,
                                       unsigned a2, unsigned a3,
                                       unsigned b0, unsigned b1) {
    asm volatile(
        "mma.sync.aligned.m16n8k16.row.col.f32.bf16.bf16.f32 "
        "{%0,%1,%2,%3}, {%4,%5,%6,%7}, {%8,%9}, {%0,%1,%2,%3};"
        : "+f"(d[0]), "+f"(d[1]), "+f"(d[2]), "+f"(d[3])
        : "r"(a0), "r"(a1), "r"(a2), "r"(a3), "r"(b0), "r"(b1));
}
__device__ __forceinline__ void mma_f16(float d[4], const unsigned a[4],
                                        unsigned b0, unsigned b1) {
    asm volatile(
        "mma.sync.aligned.m16n8k16.row.col.f32.f16.f16.f32 "
        "{%0,%1,%2,%3}, {%4,%5,%6,%7}, {%8,%9}, {%0,%1,%2,%3};"
        : "+f"(d[0]), "+f"(d[1]), "+f"(d[2]), "+f"(d[3])
        : "r"(a[0]), "r"(a[1]), "r"(a[2]), "r"(a[3]), "r"(b0), "r"(b1));
}
#define CP16(dst, src) \
    asm volatile("cp.async.ca.shared.global [%0], [%1], 16;" :: "r"(dst), "l"(src))
#define CP_COMMIT() asm volatile("cp.async.commit_group;" ::: "memory")
#define CP_WAIT(n)  asm volatile("cp.async.wait_group %0;" :: "n"(n) : "memory")

// ---------------------------------------------------------------------------
// QKV GEMM via mma.sync m16n8k16 bf16x3. CTA 128x128, warp tile 64x32.
// epilogue writes fp16 split Q/K/V (+ f32 V for resid)
// ---------------------------------------------------------------------------
#define AST 40
#define STG 40960

__global__ __launch_bounds__(256)
void qkv_gemm_mma(const float* __restrict__ X)
{
    extern __shared__ __align__(16) char smraw[];
    const int tid = threadIdx.x;
    const int wid = tid >> 5, lane = tid & 31;
    const int row0 = blockIdx.x * 128;
    const int col0 = blockIdx.y * 128;
    const int M = BATCH * SEQ;
    const int wm = wid >> 2, wn = wid & 3;
    const int m_base = wm * 64, n_base = wn * 32;

    const uint32_t sbase = smem_u32(smraw);
    const uint32_t aoff = ((m_base + (lane & 15)) * AST + (lane >> 4) * 8) * 2;
    const uint32_t boff = ((n_base + (lane >> 4) * 8 + (lane & 7)) * AST
                           + ((lane >> 3) & 1) * 8) * 2;

    float d[4][4][4];
#pragma unroll
    for (int i = 0; i < 4; i++)
#pragma unroll
        for (int j = 0; j < 4; j++)
#pragma unroll
            for (int c = 0; c < 4; c++) d[i][j][c] = 0.f;

    float4 xa[4]; uint2 wh4[4], wl4[4];

    auto load_chunk = [&](int kc) {
        const int k0 = kc * 32;
#pragma unroll
        for (int it = 0; it < 4; it++) {
            int idx = tid + it * 256;
            int r = idx >> 3, c4 = (idx & 7) * 4;
            int gr = row0 + r; if (gr >= M) gr = M - 1;
            xa[it]  = *(const float4*)(X + gr * DIMIN + k0 + c4);
            wh4[it] = *(const uint2*)(g_Wth + (col0 + r) * DIMIN + k0 + c4);
            wl4[it] = *(const uint2*)(g_Wtl + (col0 + r) * DIMIN + k0 + c4);
        }
    };
    auto store_stage = [&](int s) {
        char* st = smraw + s * STG;
#pragma unroll
        for (int it = 0; it < 4; it++) {
            int idx = tid + it * 256;
            int r = idx >> 3, c4 = (idx & 7) * 4;
            int off = (r * AST + c4) * 2;
            __nv_bfloat16 h0, l0, h1, l1, h2, l2, h3, l3;
            bsplit(xa[it].x, h0, l0); bsplit(xa[it].y, h1, l1);
            bsplit(xa[it].z, h2, l2); bsplit(xa[it].w, h3, l3);
            uint2 ah; ah.x = packbf2(h0, h1); ah.y = packbf2(h2, h3);
            uint2 al; al.x = packbf2(l0, l1); al.y = packbf2(l2, l3);
            *(uint2*)(st + off)             = ah;
            *(uint2*)(st + 10240 + off)     = al;
            *(uint2*)(st + 20480 + off)     = wh4[it];
            *(uint2*)(st + 30720 + off)     = wl4[it];
        }
    };

    load_chunk(0);
    store_stage(0);
    __syncthreads();

    for (int kc = 0; kc < 16; kc++) {
        const int cur = kc & 1;
        const bool more = (kc < 15);
        if (more) load_chunk(kc + 1);

        const uint32_t stg = sbase + cur * STG;
#pragma unroll
        for (int kk = 0; kk < 2; kk++) {
            const uint32_t kkb = kk * 32;
            unsigned bh[4][2], bl[4][2];
            ldmx4(bh[0][0], bh[0][1], bh[1][0], bh[1][1], stg + 20480 + boff + kkb);
            ldmx4(bh[2][0], bh[2][1], bh[3][0], bh[3][1], stg + 20480 + boff + kkb + 16 * AST * 2);
            ldmx4(bl[0][0], bl[0][1], bl[1][0], bl[1][1], stg + 30720 + boff + kkb);
            ldmx4(bl[2][0], bl[2][1], bl[3][0], bl[3][1], stg + 30720 + boff + kkb + 16 * AST * 2);
#pragma unroll
            for (int mi = 0; mi < 4; mi++) {
                unsigned a0, a1, a2, a3, l0, l1, l2, l3;
                ldmx4(a0, a1, a2, a3, stg + aoff + kkb + mi * 16 * AST * 2);
                ldmx4(l0, l1, l2, l3, stg + 10240 + aoff + kkb + mi * 16 * AST * 2);
#pragma unroll
                for (int ni = 0; ni < 4; ni++) {
                    mma_bf(d[mi][ni], a0, a1, a2, a3, bh[ni][0], bh[ni][1]);
                    mma_bf(d[mi][ni], a0, a1, a2, a3, bl[ni][0], bl[ni][1]);
                    mma_bf(d[mi][ni], l0, l1, l2, l3, bh[ni][0], bh[ni][1]);
                }
            }
        }
        if (more) {
            store_stage(cur ^ 1);
            __syncthreads();
        }
    }

    // epilogue: split fp16 writes (+ f32 V)
    const int gid = lane >> 2, tq = lane & 3;
#pragma unroll
    for (int mi = 0; mi < 4; mi++) {
#pragma unroll
        for (int ni = 0; ni < 4; ni++) {
            int gc = col0 + n_base + ni * 8 + tq * 2;
            int which = gc >> 9;
            int hh = (gc >> 6) & 7;
            int dd = gc & 63;
            float sc = (which == 0) ? QK_SCALE : 1.f;
            __half* dh = (which == 0) ? g_Qh : (which == 1) ? g_Kh : g_Vh;
            __half* dl = (which == 0) ? g_Ql : (which == 1) ? g_Kl : g_Vl;
#pragma unroll
            for (int hrow = 0; hrow < 2; hrow++) {
                int m = row0 + m_base + mi * 16 + gid + hrow * 8;
                if (m >= M) continue;
                int bb = m / SEQ, pos = m % SEQ;
                int idx = ((bb * NH + hh) * SEQ + pos) * HD + dd;
                float f0 = d[mi][ni][hrow * 2 + 0] * sc;
                float f1 = d[mi][ni][hrow * 2 + 1] * sc;
                __half h0 = __float2half_rn(f0), h1 = __float2half_rn(f1);
                *(unsigned*)(dh + idx) = packh2(h0, h1);
                *(unsigned*)(dl + idx) = packh2(
                    __float2half_rn(f0 - __half2float(h0)),
                    __float2half_rn(f1 - __half2float(h1)));
                if (which == 2) { float2 v; v.x = f0; v.y = f1;
                                  *(float2*)(g_V + idx) = v; }
            }
        }
    }
}

// ---------------------------------------------------------------------------
// Fused attention on mma.sync (fp16 x2-split), flash-style.
// CTA = 128 threads (4 warps), q-tile 64, k-tile 64.
// ---------------------------------------------------------------------------
#define ATT_ST 72            // halves per smem row
#define T_ROW (64 * ATT_ST)  // 4608 halves per 64x64 tile
#define QH_OFF 0
#define QL_OFF T_ROW
#define STG0_OFF (2 * T_ROW)
#define STGSZ (4 * T_ROW)

struct TileD { int kor; int vb; int nk; int mode; bool wrap; };
// mode: 0 = STATS (gene keys), 1 = inner-softmax probs, 2 = RAW

__device__ __forceinline__ TileD tdesc(bool is_img, int t) {
    TileD td;
    if (!is_img) {
        td.kor = t * 64;
        td.nk  = (SEQ - td.kor) < 64 ? (SEQ - td.kor) : 64;
        td.vb  = td.kor + NGENE;
        td.mode = 2; td.wrap = true;
    } else if (t < 16) {
        td.kor = NIMG + t * 64; td.nk = 64; td.vb = 0; td.mode = 0; td.wrap = false;
    } else if (t < 32) {
        td.kor = NIMG + (t - 16) * 64; td.nk = 64; td.vb = (t - 16) * 64;
        td.mode = 1; td.wrap = false;
    } else {
        td.kor = (t - 32) * 64;
        td.nk  = (NIMG - td.kor) < 64 ? (NIMG - td.kor) : 64;
        td.vb  = td.kor + NGENE;
        td.mode = 2; td.wrap = false;
    }
    return td;
}

__global__ __launch_bounds__(128)
void attn_mma(float* __restrict__ out)
{
    extern __shared__ __align__(16) __half smh[];
    const int tid = threadIdx.x;
    const int lane = tid & 31, wid = tid >> 5;
    const int tq = lane & 3;
    const int bh = blockIdx.x, qt = blockIdx.y;
    const int bhoff = bh * SEQ * HD;

    const bool is_img = (qt >= 16);
    int qorig0, tbase, nq;
    if (!is_img) { qorig0 = NIMG + qt * 64; tbase = qt * 64; nq = 64; }
    else {
        int i0 = (qt - 16) * 64;
        qorig0 = i0; tbase = NGENE + i0;
        nq = NIMG - i0; if (nq > 64) nq = 64;
    }
    const int ntiles = is_img ? 37 : 21;
    const uint32_t sb = smem_u32(smh);

    // ---- issue Q tiles (Qh,Ql) via cp.async ----
#pragma unroll
    for (int i = 0; i < 8; i++) {
        int id = tid + i * 128;
        int arr = id >> 9, rem = id & 511;
        int row = rem >> 3, c8 = (rem & 7) * 8;
        int tok = qorig0 + (row < nq ? row : nq - 1);
        const __half* src = (arr ? g_Ql : g_Qh) + bhoff + tok * HD + c8;
        uint32_t dst = sb + ((arr ? QL_OFF : QH_OFF) + row * ATT_ST + c8) * 2;
        CP16(dst, src);
    }
    CP_COMMIT();

    auto issue_kv = [&](int t, int s) {
        TileD td = tdesc(is_img, t);
        uint32_t stg = sb + (STG0_OFF + s * STGSZ) * 2;
#pragma unroll
        for (int i = 0; i < 16; i++) {
            int id = tid + i * 128;
            int arr = id >> 9, rem = id & 511;
            int row = rem >> 3, c8 = (rem & 7) * 8;
            int rc = row < td.nk ? row : td.nk - 1;
            const __half* src;
            if (arr < 2) {
                src = (arr ? g_Kl : g_Kh) + bhoff + (td.kor + rc) * HD + c8;
            } else {
                int vi = td.vb + rc;
                if (td.wrap && vi >= SEQ) vi -= SEQ;
                src = (arr == 3 ? g_Vl : g_Vh) + bhoff + vi * HD + c8;
            }
            uint32_t dst = stg + (arr * T_ROW + row * ATT_ST + c8) * 2;
            CP16(dst, src);
        }
        CP_COMMIT();
    };

    issue_kv(0, 0);
    CP_WAIT(1);            // Q done (stage0 may be in flight)
    __syncthreads();

    // ---- Q A-fragments (held in regs for the whole kernel) ----
    const int wm = wid;    // warp m-tile
    unsigned qa_h[4][4], qa_l[4][4];
    {
        uint32_t aoff = sb + (((wm * 16 + (lane & 15)) * ATT_ST + (lane >> 4) * 8)) * 2;
#pragma unroll
        for (int c = 0; c < 4; c++) {
            ldmx4(qa_h[c][0], qa_h[c][1], qa_h[c][2], qa_h[c][3], aoff + c * 32);
            ldmx4(qa_l[c][0], qa_l[c][1], qa_l[c][2], qa_l[c][3],
                  aoff + QL_OFF * 2 + c * 32);
        }
    }

    float O[8][4];
#pragma unroll
    for (int j = 0; j < 8; j++)
#pragma unroll
        for (int c = 0; c < 4; c++) O[j][c] = 0.f;
    float m0 = -INFINITY, m1 = -INFINITY, l0 = 0.f, l1 = 0.f;
    float mg0 = -INFINITY, mg1 = -INFINITY, lg0 = 0.f, lg1 = 0.f;
    float ivl0 = 0.f, ivl1 = 0.f;

    // per-lane ldmatrix address components
    const uint32_t krow = (lane >> 4) * 8 + (lane & 7);       // for K (n-rows)
    const uint32_t ksel = ((lane >> 3) & 1) * 8;              // k halves
    const uint32_t vrow = ((lane >> 3) & 1) * 8 + (lane & 7); // for V (k-rows)
    const uint32_t vcol = (lane >> 4) * 8;

    for (int t = 0; t < ntiles; t++) {
        const int cur = t & 1;
        const bool more = (t + 1 < ntiles);
        TileD td = tdesc(is_img, t);
        if (more) issue_kv(t + 1, cur ^ 1);
        if (more) CP_WAIT(1); else CP_WAIT(0);
        __syncthreads();

        const uint32_t stg = sb + (STG0_OFF + cur * STGSZ) * 2;

        // ---- S = Q K^T (3-term fp16 split) ----
        float S[8][4];
#pragma unroll
        for (int j = 0; j < 8; j++)
#pragma unroll
            for (int c = 0; c < 4; c++) S[j][c] = 0.f;
#pragma unroll
        for (int jj = 0; jj < 4; jj++) {
            uint32_t rb = (jj * 16 + krow) * ATT_ST;
#pragma unroll
            for (int c = 0; c < 4; c++) {
                uint32_t ad = stg + ((rb + c * 16 + ksel)) * 2;
                unsigned b0, b1, b2, b3, c0, c1, c2, c3;
                ldmx4(b0, b1, b2, b3, ad);                    // Kh
                ldmx4(c0, c1, c2, c3, ad + T_ROW * 2);        // Kl
                mma_f16(S[2*jj],   qa_h[c], b0, b1);
                mma_f16(S[2*jj+1], qa_h[c], b2, b3);
                mma_f16(S[2*jj],   qa_h[c], c0, c1);
                mma_f16(S[2*jj+1], qa_h[c], c2, c3);
                mma_f16(S[2*jj],   qa_l[c], b0, b1);
                mma_f16(S[2*jj+1], qa_l[c], b2, b3);
            }
        }

        if (td.mode == 0) {
            // inner-softmax stats over gene keys (rows: r0=lane>>2, r1=r0+8)
            float tm0 = -INFINITY, tm1 = -INFINITY;
#pragma unroll
            for (int j = 0; j < 8; j++) {
                tm0 = fmaxf(tm0, fmaxf(S[j][0], S[j][1]));
                tm1 = fmaxf(tm1, fmaxf(S[j][2], S[j][3]));
            }
            tm0 = fmaxf(tm0, __shfl_xor_sync(0xffffffffu, tm0, 1));
            tm0 = fmaxf(tm0, __shfl_xor_sync(0xffffffffu, tm0, 2));
            tm1 = fmaxf(tm1, __shfl_xor_sync(0xffffffffu, tm1, 1));
            tm1 = fmaxf(tm1, __shfl_xor_sync(0xffffffffu, tm1, 2));
            float mn0 = fmaxf(mg0, tm0), mn1 = fmaxf(mg1, tm1);
            float rs0 = 0.f, rs1 = 0.f;
#pragma unroll
            for (int j = 0; j < 8; j++) {
                rs0 += __expf(S[j][0] - mn0) + __expf(S[j][1] - mn0);
                rs1 += __expf(S[j][2] - mn1) + __expf(S[j][3] - mn1);
            }
            rs0 += __shfl_xor_sync(0xffffffffu, rs0, 1);
            rs0 += __shfl_xor_sync(0xffffffffu, rs0, 2);
            rs1 += __shfl_xor_sync(0xffffffffu, rs1, 1);
            rs1 += __shfl_xor_sync(0xffffffffu, rs1, 2);
            lg0 = lg0 * __expf(mg0 - mn0) + rs0; mg0 = mn0;
            lg1 = lg1 * __expf(mg1 - mn1) + rs1; mg1 = mn1;
        } else {
            if (is_img && t == 16) { ivl0 = 1.f / lg0; ivl1 = 1.f / lg1; }
            if (td.mode == 1) {
#pragma unroll
                for (int j = 0; j < 8; j++) {
                    S[j][0] = __expf(S[j][0] - mg0) * ivl0;
                    S[j][1] = __expf(S[j][1] - mg0) * ivl0;
                    S[j][2] = __expf(S[j][2] - mg1) * ivl1;
                    S[j][3] = __expf(S[j][3] - mg1) * ivl1;
                }
            } else if (td.nk < 64) {
#pragma unroll
                for (int j = 0; j < 8; j++) {
                    int c0 = j * 8 + tq * 2;
                    if (c0     >= td.nk) { S[j][0] = -INFINITY; S[j][2] = -INFINITY; }
                    if (c0 + 1 >= td.nk) { S[j][1] = -INFINITY; S[j][3] = -INFINITY; }
                }
            }
            // online softmax
            float tm0 = -INFINITY, tm1 = -INFINITY;
#pragma unroll
            for (int j = 0; j < 8; j++) {
                tm0 = fmaxf(tm0, fmaxf(S[j][0], S[j][1]));
                tm1 = fmaxf(tm1, fmaxf(S[j][2], S[j][3]));
            }
            tm0 = fmaxf(tm0, __shfl_xor_sync(0xffffffffu, tm0, 1));
            tm0 = fmaxf(tm0, __shfl_xor_sync(0xffffffffu, tm0, 2));
            tm1 = fmaxf(tm1, __shfl_xor_sync(0xffffffffu, tm1, 1));
            tm1 = fmaxf(tm1, __shfl_xor_sync(0xffffffffu, tm1, 2));
            float mn0 = fmaxf(m0, tm0), mn1 = fmaxf(m1, tm1);
            float sc0 = __expf(m0 - mn0), sc1 = __expf(m1 - mn1);
            float rs0 = 0.f, rs1 = 0.f;
#pragma unroll
            for (int j = 0; j < 8; j++) {
                S[j][0] = __expf(S[j][0] - mn0); rs0 += S[j][0];
                S[j][1] = __expf(S[j][1] - mn0); rs0 += S[j][1];
                S[j][2] = __expf(S[j][2] - mn1); rs1 += S[j][2];
                S[j][3] = __expf(S[j][3] - mn1); rs1 += S[j][3];
            }
            rs0 += __shfl_xor_sync(0xffffffffu, rs0, 1);
            rs0 += __shfl_xor_sync(0xffffffffu, rs0, 2);
            rs1 += __shfl_xor_sync(0xffffffffu, rs1, 1);
            rs1 += __shfl_xor_sync(0xffffffffu, rs1, 2);
            l0 = l0 * sc0 + rs0; m0 = mn0;
            l1 = l1 * sc1 + rs1; m1 = mn1;
#pragma unroll
            for (int j = 0; j < 8; j++) {
                O[j][0] *= sc0; O[j][1] *= sc0;
                O[j][2] *= sc1; O[j][3] *= sc1;
            }
            // P fragments (A, m16k16): hi + lo.
            // q loop emits exactly {a0,a1,a2,a3}: a0=(r0,k0) a1=(r0+8,k0)
            // a2=(r0,k8) a3=(r0+8,k8) — no reorder needed.
            unsigned pha[4][4], pla[4][4];
#pragma unroll
            for (int kk = 0; kk < 4; kk++) {
#pragma unroll
                for (int q = 0; q < 4; q++) {
                    int j = 2 * kk + (q >> 1);
                    int i0 = (q & 1) ? 2 : 0;
                    float f0 = S[j][i0], f1 = S[j][i0 + 1];
                    __half h0 = __float2half_rn(f0), h1 = __float2half_rn(f1);
                    pha[kk][q] = packh2(h0, h1);
                    pla[kk][q] = packh2(__float2half_rn(f0 - __half2float(h0)),
                                        __float2half_rn(f1 - __half2float(h1)));
                }
            }
            // ---- O += P V (3-term) ----
#pragma unroll
            for (int kk = 0; kk < 4; kk++) {
                uint32_t rb = (kk * 16 + vrow) * ATT_ST + vcol;
#pragma unroll
                for (int dp = 0; dp < 4; dp++) {
                    uint32_t ad = stg + (2 * T_ROW + rb + dp * 16) * 2;
                    unsigned v0, v1, v2, v3, w0, w1, w2, w3;
                    ldmx4t(v0, v1, v2, v3, ad);               // Vh
                    ldmx4t(w0, w1, w2, w3, ad + T_ROW * 2);   // Vl
                    mma_f16(O[2*dp],   pha[kk], v0, v1);
                    mma_f16(O[2*dp+1], pha[kk], v2, v3);
                    mma_f16(O[2*dp],   pha[kk], w0, w1);
                    mma_f16(O[2*dp+1], pha[kk], w2, w3);
                    mma_f16(O[2*dp],   pla[kk], v0, v1);
                    mma_f16(O[2*dp+1], pla[kk], v2, v3);
                }
            }
        }
        __syncthreads();
    }

    // ---- epilogue ----
    const int bb = bh >> 3, hh = bh & 7;
    const int r0 = wm * 16 + (lane >> 2), r1 = r0 + 8;
    float inv0 = 1.f / l0, inv1 = 1.f / l1;
#pragma unroll
    for (int dj = 0; dj < 8; dj++) {
        int d0 = dj * 8 + tq * 2;
        if (r0 < nq) {
            float2 o; o.x = O[dj][0] * inv0; o.y = O[dj][1] * inv0;
            *(float2*)(out + ((long)(bb * SEQ + tbase + r0) * (NH * HD)) + hh * HD + d0) = o;
        }
        if (r1 < nq) {
            float2 o; o.x = O[dj][2] * inv1; o.y = O[dj][3] * inv1;
            *(float2*)(out + ((long)(bb * SEQ + tbase + r1) * (NH * HD)) + hh * HD + d0) = o;
        }
    }
}

// ---------------------------------------------------------------------------
// Kernel 3: depthwise conv residual (unchanged)
// ---------------------------------------------------------------------------
__global__ __launch_bounds__(256)
void resid_kernel(const float* __restrict__ wres, float* __restrict__ out)
{
    const int blk = blockIdx.x;
    const int sb = blk % 21;
    const int bh = blk / 21;
    const int bb = bh >> 3, hh = bh & 7;
    const int dd = threadIdx.x & 63;
    const int s = sb * 4 + (threadIdx.x >> 6);
    const int t0 = s * 16;
    if (t0 >= SEQ) return;

    const float* __restrict__ v = g_V + ((bb * NH + hh) * SEQ) * HD + dd;
    const float* __restrict__ w = wres + hh * KW;

    float win[48];
#pragma unroll
    for (int i = 0; i < 48; i++) {
        int p = t0 - KPAD + i;
        win[i] = (p >= 0 && p < SEQ) ? v[p * HD] : 0.f;
    }
    float o[16];
#pragma unroll
    for (int i = 0; i < 16; i++) o[i] = 0.f;
#pragma unroll
    for (int k = 0; k < KW; k++) {
        float wk = __ldg(w + k);
#pragma unroll
        for (int i = 0; i < 16; i++) o[i] += wk * win[i + k];
    }
#pragma unroll
    for (int i = 0; i < 16; i++) {
        int t = t0 + i;
        if (t < SEQ) {
            int oi = (bb * SEQ + t) * (NH * HD) + hh * HD + dd;
            out[oi] += o[i];
        }
    }
}

// ---------------------------------------------------------------------------
extern "C" void kernel_launch(void* const* d_in, const int* in_sizes, int n_in,
                              void* d_out, int out_size)
{
    const float* x     = (const float*)d_in[0];
    const float* w_qkv = (const float*)d_in[1];
    const float* w_res = (const float*)d_in[2];
    float* out = (float*)d_out;

    const int gemm_smem = 2 * STG;                            // 81920 B
    cudaFuncSetAttribute(qkv_gemm_mma, cudaFuncAttributeMaxDynamicSharedMemorySize, gemm_smem);
    const int attn_smem = (2 * T_ROW + 2 * STGSZ) * 2;        // 92160 B
    cudaFuncSetAttribute(attn_mma, cudaFuncAttributeMaxDynamicSharedMemorySize, attn_smem);

    dim3 gp(NOUTC / 32, DIMIN / 32);
    prep_w_kernel<<<gp, dim3(32, 8)>>>(w_qkv);

    dim3 g1((BATCH * SEQ + 127) / 128, NOUTC / 128);
    qkv_gemm_mma<<<g1, 256, gemm_smem>>>(x);

    dim3 g2(BATCH * NH, 21);
    attn_mma<<<g2, 128, attn_smem>>>(out);

    resid_kernel<<<BATCH * NH * 21, 256>>>(w_res, out);
}

// round 10
// speedup vs baseline: 3.8471x; 1.3342x over previous
#include <cuda_runtime.h>
#include <cuda_bf16.h>
#include <cuda_fp16.h>
#include <math.h>
#include <stdint.h>

#define BATCH 8
#define SEQ   1315
#define DIMIN 512
#define NOUTC 1536
#define NH    8
#define HD    64
#define NIMG  291
#define NGENE 1024
#define KW    33
#define KPAD  16
#define QK_SCALE 0.125f

// scratch (allocation-free rule: __device__ globals)
__device__ float g_V [BATCH*NH*SEQ*HD];                 // f32 V for resid conv
__device__ __half g_Qh[BATCH*NH*SEQ*HD], g_Ql[BATCH*NH*SEQ*HD];
__device__ __half g_Kh[BATCH*NH*SEQ*HD];
__device__ __half g_Vh[BATCH*NH*SEQ*HD];
__device__ __nv_bfloat16 g_Wth[NOUTC*DIMIN];   // [n][k] bf16 hi
__device__ __nv_bfloat16 g_Wtl[NOUTC*DIMIN];   // [n][k] bf16 lo

__device__ __forceinline__ uint32_t smem_u32(const void* p) {
    uint32_t a;
    asm("{ .reg .u64 t; cvta.to.shared.u64 t, %1; cvt.u32.u64 %0, t; }"
        : "=r"(a) : "l"(p));
    return a;
}
__device__ __forceinline__ void bsplit(float x, __nv_bfloat16& h, __nv_bfloat16& l) {
    h = __float2bfloat16(x);
    l = __float2bfloat16(x - __bfloat162float(h));
}
__device__ __forceinline__ unsigned packbf2(__nv_bfloat16 a, __nv_bfloat16 b) {
    __nv_bfloat162 t(a, b);
    return *(unsigned*)&t;
}
__device__ __forceinline__ unsigned packh2(__half a, __half b) {
    __half2 t = __halves2half2(a, b);
    return *(unsigned*)&t;
}

// ---------------------------------------------------------------------------
// prep: W[512][1536] f32 -> Wth/Wtl[1536][512] bf16 (transpose + split)
// ---------------------------------------------------------------------------
__global__ void prep_w_kernel(const float* __restrict__ W)
{
    __shared__ float t[32][33];
    const int n0 = blockIdx.x * 32, k0 = blockIdx.y * 32;
    const int tx = threadIdx.x, ty = threadIdx.y;
#pragma unroll
    for (int r = 0; r < 4; r++)
        t[ty + 8 * r][tx] = W[(k0 + ty + 8 * r) * NOUTC + n0 + tx];
    __syncthreads();
#pragma unroll
    for (int r = 0; r < 4; r++) {
        float v = t[tx][ty + 8 * r];
        __nv_bfloat16 h, l;
        bsplit(v, h, l);
        int o = (n0 + ty + 8 * r) * DIMIN + k0 + tx;
        g_Wth[o] = h;
        g_Wtl[o] = l;
    }
}

// ---------------------------------------------------------------------------
// common MMA helpers
// ---------------------------------------------------------------------------
__device__ __forceinline__ void ldmx4(unsigned& r0, unsigned& r1, unsigned& r2,
                                      unsigned& r3, uint32_t addr) {
    asm volatile("ldmatrix.sync.aligned.m8n8.x4.shared.b16 {%0,%1,%2,%3}, [%4];"
                 : "=r"(r0), "=r"(r1), "=r"(r2), "=r"(r3) : "r"(addr));
}
__device__ __forceinline__ void ldmx4t(unsigned& r0, unsigned& r1, unsigned& r2,
                                       unsigned& r3, uint32_t addr) {
    asm volatile("ldmatrix.sync.aligned.m8n8.x4.trans.shared.b16 {%0,%1,%2,%3}, [%4];"
                 : "=r"(r0), "=r"(r1), "=r"(r2), "=r"(r3) : "r"(addr));
}
__device__ __forceinline__ void mma_bf(float d[4], unsigned a0, unsigned a1,
                                       unsigned a2, unsigned a3,
                                       unsigned b0, unsigned b1) {
    asm volatile(
        "mma.sync.aligned.m16n8k16.row.col.f32.bf16.bf16.f32 "
        "{%0,%1,%2,%3}, {%4,%5,%6,%7}, {%8,%9}, {%0,%1,%2,%3};"
        : "+f"(d[0]), "+f"(d[1]), "+f"(d[2]), "+f"(d[3])
        : "r"(a0), "r"(a1), "r"(a2), "r"(a3), "r"(b0), "r"(b1));
}
__device__ __forceinline__ void mma_f16(float d[4], const unsigned a[4],
                                        unsigned b0, unsigned b1) {
    asm volatile(
        "mma.sync.aligned.m16n8k16.row.col.f32.f16.f16.f32 "
        "{%0,%1,%2,%3}, {%4,%5,%6,%7}, {%8,%9}, {%0,%1,%2,%3};"
        : "+f"(d[0]), "+f"(d[1]), "+f"(d[2]), "+f"(d[3])
        : "r"(a[0]), "r"(a[1]), "r"(a[2]), "r"(a[3]), "r"(b0), "r"(b1));
}
#define CP16(dst, src) \
    asm volatile("cp.async.ca.shared.global [%0], [%1], 16;" :: "r"(dst), "l"(src))
#define CP_COMMIT() asm volatile("cp.async.commit_group;" ::: "memory")
#define CP_WAIT(n)  asm volatile("cp.async.wait_group %0;" :: "n"(n) : "memory")

// ---------------------------------------------------------------------------
// QKV GEMM via mma.sync m16n8k16 bf16x3. CTA 128x128, warp tile 64x32.
// epilogue: Q -> fp16 hi+lo, K/V -> fp16 hi only, V also f32 (for resid)
// ---------------------------------------------------------------------------
#define AST 40
#define STG 40960

__global__ __launch_bounds__(256)
void qkv_gemm_mma(const float* __restrict__ X)
{
    extern __shared__ __align__(16) char smraw[];
    const int tid = threadIdx.x;
    const int wid = tid >> 5, lane = tid & 31;
    const int row0 = blockIdx.x * 128;
    const int col0 = blockIdx.y * 128;
    const int M = BATCH * SEQ;
    const int wm = wid >> 2, wn = wid & 3;
    const int m_base = wm * 64, n_base = wn * 32;

    const uint32_t sbase = smem_u32(smraw);
    const uint32_t aoff = ((m_base + (lane & 15)) * AST + (lane >> 4) * 8) * 2;
    const uint32_t boff = ((n_base + (lane >> 4) * 8 + (lane & 7)) * AST
                           + ((lane >> 3) & 1) * 8) * 2;

    float d[4][4][4];
#pragma unroll
    for (int i = 0; i < 4; i++)
#pragma unroll
        for (int j = 0; j < 4; j++)
#pragma unroll
            for (int c = 0; c < 4; c++) d[i][j][c] = 0.f;

    float4 xa[4]; uint2 wh4[4], wl4[4];

    auto load_chunk = [&](int kc) {
        const int k0 = kc * 32;
#pragma unroll
        for (int it = 0; it < 4; it++) {
            int idx = tid + it * 256;
            int r = idx >> 3, c4 = (idx & 7) * 4;
            int gr = row0 + r; if (gr >= M) gr = M - 1;
            xa[it]  = *(const float4*)(X + gr * DIMIN + k0 + c4);
            wh4[it] = *(const uint2*)(g_Wth + (col0 + r) * DIMIN + k0 + c4);
            wl4[it] = *(const uint2*)(g_Wtl + (col0 + r) * DIMIN + k0 + c4);
        }
    };
    auto store_stage = [&](int s) {
        char* st = smraw + s * STG;
#pragma unroll
        for (int it = 0; it < 4; it++) {
            int idx = tid + it * 256;
            int r = idx >> 3, c4 = (idx & 7) * 4;
            int off = (r * AST + c4) * 2;
            __nv_bfloat16 h0, l0, h1, l1, h2, l2, h3, l3;
            bsplit(xa[it].x, h0, l0); bsplit(xa[it].y, h1, l1);
            bsplit(xa[it].z, h2, l2); bsplit(xa[it].w, h3, l3);
            uint2 ah; ah.x = packbf2(h0, h1); ah.y = packbf2(h2, h3);
            uint2 al; al.x = packbf2(l0, l1); al.y = packbf2(l2, l3);
            *(uint2*)(st + off)             = ah;
            *(uint2*)(st + 10240 + off)     = al;
            *(uint2*)(st + 20480 + off)     = wh4[it];
            *(uint2*)(st + 30720 + off)     = wl4[it];
        }
    };

    load_chunk(0);
    store_stage(0);
    __syncthreads();

    for (int kc = 0; kc < 16; kc++) {
        const int cur = kc & 1;
        const bool more = (kc < 15);
        if (more) load_chunk(kc + 1);

        const uint32_t stg = sbase + cur * STG;
#pragma unroll
        for (int kk = 0; kk < 2; kk++) {
            const uint32_t kkb = kk * 32;
            unsigned bh[4][2], bl[4][2];
            ldmx4(bh[0][0], bh[0][1], bh[1][0], bh[1][1], stg + 20480 + boff + kkb);
            ldmx4(bh[2][0], bh[2][1], bh[3][0], bh[3][1], stg + 20480 + boff + kkb + 16 * AST * 2);
            ldmx4(bl[0][0], bl[0][1], bl[1][0], bl[1][1], stg + 30720 + boff + kkb);
            ldmx4(bl[2][0], bl[2][1], bl[3][0], bl[3][1], stg + 30720 + boff + kkb + 16 * AST * 2);
#pragma unroll
            for (int mi = 0; mi < 4; mi++) {
                unsigned a0, a1, a2, a3, l0, l1, l2, l3;
                ldmx4(a0, a1, a2, a3, stg + aoff + kkb + mi * 16 * AST * 2);
                ldmx4(l0, l1, l2, l3, stg + 10240 + aoff + kkb + mi * 16 * AST * 2);
#pragma unroll
                for (int ni = 0; ni < 4; ni++) {
                    mma_bf(d[mi][ni], a0, a1, a2, a3, bh[ni][0], bh[ni][1]);
                    mma_bf(d[mi][ni], a0, a1, a2, a3, bl[ni][0], bl[ni][1]);
                    mma_bf(d[mi][ni], l0, l1, l2, l3, bh[ni][0], bh[ni][1]);
                }
            }
        }
        if (more) {
            store_stage(cur ^ 1);
            __syncthreads();
        }
    }

    // epilogue: Q hi+lo fp16; K/V hi fp16; V f32
    const int gid = lane >> 2, tq = lane & 3;
#pragma unroll
    for (int mi = 0; mi < 4; mi++) {
#pragma unroll
        for (int ni = 0; ni < 4; ni++) {
            int gc = col0 + n_base + ni * 8 + tq * 2;
            int which = gc >> 9;
            int hh = (gc >> 6) & 7;
            int dd = gc & 63;
            float sc = (which == 0) ? QK_SCALE : 1.f;
            __half* dh = (which == 0) ? g_Qh : (which == 1) ? g_Kh : g_Vh;
#pragma unroll
            for (int hrow = 0; hrow < 2; hrow++) {
                int m = row0 + m_base + mi * 16 + gid + hrow * 8;
                if (m >= M) continue;
                int bb = m / SEQ, pos = m % SEQ;
                int idx = ((bb * NH + hh) * SEQ + pos) * HD + dd;
                float f0 = d[mi][ni][hrow * 2 + 0] * sc;
                float f1 = d[mi][ni][hrow * 2 + 1] * sc;
                __half h0 = __float2half_rn(f0), h1 = __float2half_rn(f1);
                *(unsigned*)(dh + idx) = packh2(h0, h1);
                if (which == 0) {
                    *(unsigned*)(g_Ql + idx) = packh2(
                        __float2half_rn(f0 - __half2float(h0)),
                        __float2half_rn(f1 - __half2float(h1)));
                } else if (which == 2) {
                    float2 v; v.x = f0; v.y = f1;
                    *(float2*)(g_V + idx) = v;
                }
            }
        }
    }
}

// ---------------------------------------------------------------------------
// Fused attention on mma.sync, flash-style.
// Q: fp16 hi+lo (regs); K,V: fp16 hi only; P: hi+lo (regs).
// S = qh*kh + ql*kh ; O += ph*vh + pl*vh  (2 MMA-sets each)
// CTA = 128 threads (4 warps), q-tile 64, k-tile 64, 2-stage cp.async.
// ---------------------------------------------------------------------------
#define ATT_ST 72            // halves per smem row
#define T_ROW (64 * ATT_ST)  // 4608 halves per 64x64 tile
#define QH_OFF 0
#define QL_OFF T_ROW
#define STG0_OFF (2 * T_ROW)
#define STGSZ (2 * T_ROW)    // Kh | Vh

struct TileD { int kor; int vb; int nk; int mode; bool wrap; };
// mode: 0 = STATS (gene keys), 1 = inner-softmax probs, 2 = RAW

__device__ __forceinline__ TileD tdesc(bool is_img, int t) {
    TileD td;
    if (!is_img) {
        td.kor = t * 64;
        td.nk  = (SEQ - td.kor) < 64 ? (SEQ - td.kor) : 64;
        td.vb  = td.kor + NGENE;
        td.mode = 2; td.wrap = true;
    } else if (t < 16) {
        td.kor = NIMG + t * 64; td.nk = 64; td.vb = 0; td.mode = 0; td.wrap = false;
    } else if (t < 32) {
        td.kor = NIMG + (t - 16) * 64; td.nk = 64; td.vb = (t - 16) * 64;
        td.mode = 1; td.wrap = false;
    } else {
        td.kor = (t - 32) * 64;
        td.nk  = (NIMG - td.kor) < 64 ? (NIMG - td.kor) : 64;
        td.vb  = td.kor + NGENE;
        td.mode = 2; td.wrap = false;
    }
    return td;
}

__global__ __launch_bounds__(128)
void attn_mma(float* __restrict__ out)
{
    extern __shared__ __align__(16) __half smh[];
    const int tid = threadIdx.x;
    const int lane = tid & 31, wid = tid >> 5;
    const int tq = lane & 3;
    const int bh = blockIdx.x, qt = blockIdx.y;
    const int bhoff = bh * SEQ * HD;

    const bool is_img = (qt >= 16);
    int qorig0, tbase, nq;
    if (!is_img) { qorig0 = NIMG + qt * 64; tbase = qt * 64; nq = 64; }
    else {
        int i0 = (qt - 16) * 64;
        qorig0 = i0; tbase = NGENE + i0;
        nq = NIMG - i0; if (nq > 64) nq = 64;
    }
    const int ntiles = is_img ? 37 : 21;
    const uint32_t sb = smem_u32(smh);

    // ---- issue Q tiles (Qh,Ql) via cp.async ----
#pragma unroll
    for (int i = 0; i < 8; i++) {
        int id = tid + i * 128;
        int arr = id >> 9, rem = id & 511;
        int row = rem >> 3, c8 = (rem & 7) * 8;
        int tok = qorig0 + (row < nq ? row : nq - 1);
        const __half* src = (arr ? g_Ql : g_Qh) + bhoff + tok * HD + c8;
        uint32_t dst = sb + ((arr ? QL_OFF : QH_OFF) + row * ATT_ST + c8) * 2;
        CP16(dst, src);
    }
    CP_COMMIT();

    auto issue_kv = [&](int t, int s) {
        TileD td = tdesc(is_img, t);
        uint32_t stg = sb + (STG0_OFF + s * STGSZ) * 2;
#pragma unroll
        for (int i = 0; i < 8; i++) {
            int id = tid + i * 128;
            int arr = id >> 9, rem = id & 511;   // 0 = Kh, 1 = Vh
            int row = rem >> 3, c8 = (rem & 7) * 8;
            int rc = row < td.nk ? row : td.nk - 1;
            const __half* src;
            if (arr == 0) {
                src = g_Kh + bhoff + (td.kor + rc) * HD + c8;
            } else {
                int vi = td.vb + rc;
                if (td.wrap && vi >= SEQ) vi -= SEQ;
                src = g_Vh + bhoff + vi * HD + c8;
            }
            uint32_t dst = stg + (arr * T_ROW + row * ATT_ST + c8) * 2;
            CP16(dst, src);
        }
        CP_COMMIT();
    };

    issue_kv(0, 0);
    CP_WAIT(1);            // Q done (stage0 may be in flight)
    __syncthreads();

    // ---- Q A-fragments (held in regs for the whole kernel) ----
    const int wm = wid;    // warp m-tile
    unsigned qa_h[4][4], qa_l[4][4];
    {
        uint32_t aoff = sb + (((wm * 16 + (lane & 15)) * ATT_ST + (lane >> 4) * 8)) * 2;
#pragma unroll
        for (int c = 0; c < 4; c++) {
            ldmx4(qa_h[c][0], qa_h[c][1], qa_h[c][2], qa_h[c][3], aoff + c * 32);
            ldmx4(qa_l[c][0], qa_l[c][1], qa_l[c][2], qa_l[c][3],
                  aoff + QL_OFF * 2 + c * 32);
        }
    }

    float O[8][4];
#pragma unroll
    for (int j = 0; j < 8; j++)
#pragma unroll
        for (int c = 0; c < 4; c++) O[j][c] = 0.f;
    float m0 = -INFINITY, m1 = -INFINITY, l0 = 0.f, l1 = 0.f;
    float mg0 = -INFINITY, mg1 = -INFINITY, lg0 = 0.f, lg1 = 0.f;
    float ivl0 = 0.f, ivl1 = 0.f;

    // per-lane ldmatrix address components
    const uint32_t krow = (lane >> 4) * 8 + (lane & 7);       // for K (n-rows)
    const uint32_t ksel = ((lane >> 3) & 1) * 8;              // k halves
    const uint32_t vrow = ((lane >> 3) & 1) * 8 + (lane & 7); // for V (k-rows)
    const uint32_t vcol = (lane >> 4) * 8;

    for (int t = 0; t < ntiles; t++) {
        const int cur = t & 1;
        const bool more = (t + 1 < ntiles);
        TileD td = tdesc(is_img, t);
        if (more) issue_kv(t + 1, cur ^ 1);
        if (more) CP_WAIT(1); else CP_WAIT(0);
        __syncthreads();

        const uint32_t stg = sb + (STG0_OFF + cur * STGSZ) * 2;

        // ---- S = Q K^T (2-term: qh*kh + ql*kh) ----
        float S[8][4];
#pragma unroll
        for (int j = 0; j < 8; j++)
#pragma unroll
            for (int c = 0; c < 4; c++) S[j][c] = 0.f;
#pragma unroll
        for (int jj = 0; jj < 4; jj++) {
            uint32_t rb = (jj * 16 + krow) * ATT_ST;
#pragma unroll
            for (int c = 0; c < 4; c++) {
                uint32_t ad = stg + ((rb + c * 16 + ksel)) * 2;
                unsigned b0, b1, b2, b3;
                ldmx4(b0, b1, b2, b3, ad);                    // Kh
                mma_f16(S[2*jj],   qa_h[c], b0, b1);
                mma_f16(S[2*jj+1], qa_h[c], b2, b3);
                mma_f16(S[2*jj],   qa_l[c], b0, b1);
                mma_f16(S[2*jj+1], qa_l[c], b2, b3);
            }
        }

        if (td.mode == 0) {
            // inner-softmax stats over gene keys (rows: r0=lane>>2, r1=r0+8)
            float tm0 = -INFINITY, tm1 = -INFINITY;
#pragma unroll
            for (int j = 0; j < 8; j++) {
                tm0 = fmaxf(tm0, fmaxf(S[j][0], S[j][1]));
                tm1 = fmaxf(tm1, fmaxf(S[j][2], S[j][3]));
            }
            tm0 = fmaxf(tm0, __shfl_xor_sync(0xffffffffu, tm0, 1));
            tm0 = fmaxf(tm0, __shfl_xor_sync(0xffffffffu, tm0, 2));
            tm1 = fmaxf(tm1, __shfl_xor_sync(0xffffffffu, tm1, 1));
            tm1 = fmaxf(tm1, __shfl_xor_sync(0xffffffffu, tm1, 2));
            float mn0 = fmaxf(mg0, tm0), mn1 = fmaxf(mg1, tm1);
            float rs0 = 0.f, rs1 = 0.f;
#pragma unroll
            for (int j = 0; j < 8; j++) {
                rs0 += __expf(S[j][0] - mn0) + __expf(S[j][1] - mn0);
                rs1 += __expf(S[j][2] - mn1) + __expf(S[j][3] - mn1);
            }
            rs0 += __shfl_xor_sync(0xffffffffu, rs0, 1);
            rs0 += __shfl_xor_sync(0xffffffffu, rs0, 2);
            rs1 += __shfl_xor_sync(0xffffffffu, rs1, 1);
            rs1 += __shfl_xor_sync(0xffffffffu, rs1, 2);
            lg0 = lg0 * __expf(mg0 - mn0) + rs0; mg0 = mn0;
            lg1 = lg1 * __expf(mg1 - mn1) + rs1; mg1 = mn1;
        } else {
            if (is_img && t == 16) { ivl0 = 1.f / lg0; ivl1 = 1.f / lg1; }
            if (td.mode == 1) {
#pragma unroll
                for (int j = 0; j < 8; j++) {
                    S[j][0] = __expf(S[j][0] - mg0) * ivl0;
                    S[j][1] = __expf(S[j][1] - mg0) * ivl0;
                    S[j][2] = __expf(S[j][2] - mg1) * ivl1;
                    S[j][3] = __expf(S[j][3] - mg1) * ivl1;
                }
            } else if (td.nk < 64) {
#pragma unroll
                for (int j = 0; j < 8; j++) {
                    int c0 = j * 8 + tq * 2;
                    if (c0     >= td.nk) { S[j][0] = -INFINITY; S[j][2] = -INFINITY; }
                    if (c0 + 1 >= td.nk) { S[j][1] = -INFINITY; S[j][3] = -INFINITY; }
                }
            }
            // online softmax
            float tm0 = -INFINITY, tm1 = -INFINITY;
#pragma unroll
            for (int j = 0; j < 8; j++) {
                tm0 = fmaxf(tm0, fmaxf(S[j][0], S[j][1]));
                tm1 = fmaxf(tm1, fmaxf(S[j][2], S[j][3]));
            }
            tm0 = fmaxf(tm0, __shfl_xor_sync(0xffffffffu, tm0, 1));
            tm0 = fmaxf(tm0, __shfl_xor_sync(0xffffffffu, tm0, 2));
            tm1 = fmaxf(tm1, __shfl_xor_sync(0xffffffffu, tm1, 1));
            tm1 = fmaxf(tm1, __shfl_xor_sync(0xffffffffu, tm1, 2));
            float mn0 = fmaxf(m0, tm0), mn1 = fmaxf(m1, tm1);
            float sc0 = __expf(m0 - mn0), sc1 = __expf(m1 - mn1);
            float rs0 = 0.f, rs1 = 0.f;
#pragma unroll
            for (int j = 0; j < 8; j++) {
                S[j][0] = __expf(S[j][0] - mn0); rs0 += S[j][0];
                S[j][1] = __expf(S[j][1] - mn0); rs0 += S[j][1];
                S[j][2] = __expf(S[j][2] - mn1); rs1 += S[j][2];
                S[j][3] = __expf(S[j][3] - mn1); rs1 += S[j][3];
            }
            rs0 += __shfl_xor_sync(0xffffffffu, rs0, 1);
            rs0 += __shfl_xor_sync(0xffffffffu, rs0, 2);
            rs1 += __shfl_xor_sync(0xffffffffu, rs1, 1);
            rs1 += __shfl_xor_sync(0xffffffffu, rs1, 2);
            l0 = l0 * sc0 + rs0; m0 = mn0;
            l1 = l1 * sc1 + rs1; m1 = mn1;
#pragma unroll
            for (int j = 0; j < 8; j++) {
                O[j][0] *= sc0; O[j][1] *= sc0;
                O[j][2] *= sc1; O[j][3] *= sc1;
            }
            // P fragments (A, m16k16): hi + lo; emitted directly in
            // {a0,a1,a2,a3} = {(r0,k0),(r0+8,k0),(r0,k8),(r0+8,k8)} order.
            unsigned pha[4][4], pla[4][4];
#pragma unroll
            for (int kk = 0; kk < 4; kk++) {
#pragma unroll
                for (int q = 0; q < 4; q++) {
                    int j = 2 * kk + (q >> 1);
                    int i0 = (q & 1) ? 2 : 0;
                    float f0 = S[j][i0], f1 = S[j][i0 + 1];
                    __half h0 = __float2half_rn(f0), h1 = __float2half_rn(f1);
                    pha[kk][q] = packh2(h0, h1);
                    pla[kk][q] = packh2(__float2half_rn(f0 - __half2float(h0)),
                                        __float2half_rn(f1 - __half2float(h1)));
                }
            }
            // ---- O += P V (2-term: ph*vh + pl*vh) ----
#pragma unroll
            for (int kk = 0; kk < 4; kk++) {
                uint32_t rb = (kk * 16 + vrow) * ATT_ST + vcol;
#pragma unroll
                for (int dp = 0; dp < 4; dp++) {
                    uint32_t ad = stg + (T_ROW + rb + dp * 16) * 2;
                    unsigned v0, v1, v2, v3;
                    ldmx4t(v0, v1, v2, v3, ad);               // Vh
                    mma_f16(O[2*dp],   pha[kk], v0, v1);
                    mma_f16(O[2*dp+1], pha[kk], v2, v3);
                    mma_f16(O[2*dp],   pla[kk], v0, v1);
                    mma_f16(O[2*dp+1], pla[kk], v2, v3);
                }
            }
        }
        __syncthreads();
    }

    // ---- epilogue ----
    const int bb = bh >> 3, hh = bh & 7;
    const int r0 = wm * 16 + (lane >> 2), r1 = r0 + 8;
    float inv0 = 1.f / l0, inv1 = 1.f / l1;
#pragma unroll
    for (int dj = 0; dj < 8; dj++) {
        int d0 = dj * 8 + tq * 2;
        if (r0 < nq) {
            float2 o; o.x = O[dj][0] * inv0; o.y = O[dj][1] * inv0;
            *(float2*)(out + ((long)(bb * SEQ + tbase + r0) * (NH * HD)) + hh * HD + d0) = o;
        }
        if (r1 < nq) {
            float2 o; o.x = O[dj][2] * inv1; o.y = O[dj][3] * inv1;
            *(float2*)(out + ((long)(bb * SEQ + tbase + r1) * (NH * HD)) + hh * HD + d0) = o;
        }
    }
}

// ---------------------------------------------------------------------------
// Kernel 3: depthwise conv residual, strips of 8 (better latency hiding)
// ---------------------------------------------------------------------------
#define NSB 42   // ceil(ceil(1315/8)=165 strips / 4 per block)

__global__ __launch_bounds__(256)
void resid_kernel(const float* __restrict__ wres, float* __restrict__ out)
{
    const int blk = blockIdx.x;
    const int sb = blk % NSB;
    const int bh = blk / NSB;
    const int bb = bh >> 3, hh = bh & 7;
    const int dd = threadIdx.x & 63;
    const int s = sb * 4 + (threadIdx.x >> 6);
    const int t0 = s * 8;
    if (t0 >= SEQ) return;

    const float* __restrict__ v = g_V + ((bb * NH + hh) * SEQ) * HD + dd;
    const float* __restrict__ w = wres + hh * KW;

    float win[40];
#pragma unroll
    for (int i = 0; i < 40; i++) {
        int p = t0 - KPAD + i;
        win[i] = (p >= 0 && p < SEQ) ? v[p * HD] : 0.f;
    }
    float o[8];
#pragma unroll
    for (int i = 0; i < 8; i++) o[i] = 0.f;
#pragma unroll
    for (int k = 0; k < KW; k++) {
        float wk = __ldg(w + k);
#pragma unroll
        for (int i = 0; i < 8; i++) o[i] += wk * win[i + k];
    }
#pragma unroll
    for (int i = 0; i < 8; i++) {
        int t = t0 + i;
        if (t < SEQ) {
            int oi = (bb * SEQ + t) * (NH * HD) + hh * HD + dd;
            out[oi] += o[i];
        }
    }
}

// ---------------------------------------------------------------------------
extern "C" void kernel_launch(void* const* d_in, const int* in_sizes, int n_in,
                              void* d_out, int out_size)
{
    const float* x     = (const float*)d_in[0];
    const float* w_qkv = (const float*)d_in[1];
    const float* w_res = (const float*)d_in[2];
    float* out = (float*)d_out;

    const int gemm_smem = 2 * STG;                            // 81920 B
    cudaFuncSetAttribute(qkv_gemm_mma, cudaFuncAttributeMaxDynamicSharedMemorySize, gemm_smem);
    const int attn_smem = (2 * T_ROW + 2 * STGSZ) * 2;        // 55296 B
    cudaFuncSetAttribute(attn_mma, cudaFuncAttributeMaxDynamicSharedMemorySize, attn_smem);

    dim3 gp(NOUTC / 32, DIMIN / 32);
    prep_w_kernel<<<gp, dim3(32, 8)>>>(w_qkv);

    dim3 g1((BATCH * SEQ + 127) / 128, NOUTC / 128);
    qkv_gemm_mma<<<g1, 256, gemm_smem>>>(x);

    dim3 g2(BATCH * NH, 21);
    attn_mma<<<g2, 128, attn_smem>>>(out);

    resid_kernel<<<BATCH * NH * NSB, 256>>>(w_res, out);
}

// round 11
// speedup vs baseline: 4.6913x; 1.2195x over previous
#include <cuda_runtime.h>
#include <cuda_bf16.h>
#include <cuda_fp16.h>
#include <math.h>
#include <stdint.h>

#define BATCH 8
#define SEQ   1315
#define DIMIN 512
#define NOUTC 1536
#define NH    8
#define HD    64
#define NIMG  291
#define NGENE 1024
#define KW    33
#define KPAD  16
#define QK_SCALE 0.125f

// scratch (allocation-free rule: __device__ globals)
__device__ float g_V [BATCH*NH*SEQ*HD];                 // f32 V for resid conv
__device__ __half g_Qh[BATCH*NH*SEQ*HD];
__device__ __half g_Kh[BATCH*NH*SEQ*HD];
__device__ __half g_Vh[BATCH*NH*SEQ*HD];
__device__ __nv_bfloat16 g_Wth[NOUTC*DIMIN];   // [n][k] bf16 hi
__device__ __nv_bfloat16 g_Wtl[NOUTC*DIMIN];   // [n][k] bf16 lo

__device__ __forceinline__ uint32_t smem_u32(const void* p) {
    uint32_t a;
    asm("{ .reg .u64 t; cvta.to.shared.u64 t, %1; cvt.u32.u64 %0, t; }"
        : "=r"(a) : "l"(p));
    return a;
}
__device__ __forceinline__ void bsplit(float x, __nv_bfloat16& h, __nv_bfloat16& l) {
    h = __float2bfloat16(x);
    l = __float2bfloat16(x - __bfloat162float(h));
}
__device__ __forceinline__ unsigned packbf2(__nv_bfloat16 a, __nv_bfloat16 b) {
    __nv_bfloat162 t(a, b);
    return *(unsigned*)&t;
}
__device__ __forceinline__ unsigned packh2(__half a, __half b) {
    __half2 t = __halves2half2(a, b);
    return *(unsigned*)&t;
}

// ---------------------------------------------------------------------------
// prep: W[512][1536] f32 -> Wth/Wtl[1536][512] bf16 (transpose + split)
// ---------------------------------------------------------------------------
__global__ void prep_w_kernel(const float* __restrict__ W)
{
    __shared__ float t[32][33];
    const int n0 = blockIdx.x * 32, k0 = blockIdx.y * 32;
    const int tx = threadIdx.x, ty = threadIdx.y;
#pragma unroll
    for (int r = 0; r < 4; r++)
        t[ty + 8 * r][tx] = W[(k0 + ty + 8 * r) * NOUTC + n0 + tx];
    __syncthreads();
#pragma unroll
    for (int r = 0; r < 4; r++) {
        float v = t[tx][ty + 8 * r];
        __nv_bfloat16 h, l;
        bsplit(v, h, l);
        int o = (n0 + ty + 8 * r) * DIMIN + k0 + tx;
        g_Wth[o] = h;
        g_Wtl[o] = l;
    }
}

// ---------------------------------------------------------------------------
// common MMA helpers
// ---------------------------------------------------------------------------
__device__ __forceinline__ void ldmx4(unsigned& r0, unsigned& r1, unsigned& r2,
                                      unsigned& r3, uint32_t addr) {
    asm volatile("ldmatrix.sync.aligned.m8n8.x4.shared.b16 {%0,%1,%2,%3}, [%4];"
                 : "=r"(r0), "=r"(r1), "=r"(r2), "=r"(r3) : "r"(addr));
}
__device__ __forceinline__ void ldmx4t(unsigned& r0, unsigned& r1, unsigned& r2,
                                       unsigned& r3, uint32_t addr) {
    asm volatile("ldmatrix.sync.aligned.m8n8.x4.trans.shared.b16 {%0,%1,%2,%3}, [%4];"
                 : "=r"(r0), "=r"(r1), "=r"(r2), "=r"(r3) : "r"(addr));
}
__device__ __forceinline__ void mma_bf(float d[4], unsigned a0, unsigned a1,
                                       unsigned a2, unsigned a3,
                                       unsigned b0, unsigned b1) {
    asm volatile(
        "mma.sync.aligned.m16n8k16.row.col.f32.bf16.bf16.f32 "
        "{%0,%1,%2,%3}, {%4,%5,%6,%7}, {%8,%9}, {%0,%1,%2,%3};"
        : "+f"(d[0]), "+f"(d[1]), "+f"(d[2]), "+f"(d[3])
        : "r"(a0), "r"(a1), "r"(a2), "r"(a3), "r"(b0), "r"(b1));
}
__device__ __forceinline__ void mma_f16(float d[4], const unsigned a[4],
                                        unsigned b0, unsigned b1) {
    asm volatile(
        "mma.sync.aligned.m16n8k16.row.col.f32.f16.f16.f32 "
        "{%0,%1,%2,%3}, {%4,%5,%6,%7}, {%8,%9}, {%0,%1,%2,%3};"
        : "+f"(d[0]), "+f"(d[1]), "+f"(d[2]), "+f"(d[3])
        : "r"(a[0]), "r"(a[1]), "r"(a[2]), "r"(a[3]), "r"(b0), "r"(b1));
}
#define CP16(dst, src) \
    asm volatile("cp.async.ca.shared.global [%0], [%1], 16;" :: "r"(dst), "l"(src))
#define CP_COMMIT() asm volatile("cp.async.commit_group;" ::: "memory")
#define CP_WAIT(n)  asm volatile("cp.async.wait_group %0;" :: "n"(n) : "memory")

// ---------------------------------------------------------------------------
// QKV GEMM via mma.sync m16n8k16 bf16x3. CTA 128x128, warp tile 64x32.
// epilogue: Q/K/V -> fp16 hi; V also f32 (for resid)
// ---------------------------------------------------------------------------
#define AST 40
#define STG 40960

__global__ __launch_bounds__(256)
void qkv_gemm_mma(const float* __restrict__ X)
{
    extern __shared__ __align__(16) char smraw[];
    const int tid = threadIdx.x;
    const int wid = tid >> 5, lane = tid & 31;
    const int row0 = blockIdx.x * 128;
    const int col0 = blockIdx.y * 128;
    const int M = BATCH * SEQ;
    const int wm = wid >> 2, wn = wid & 3;
    const int m_base = wm * 64, n_base = wn * 32;

    const uint32_t sbase = smem_u32(smraw);
    const uint32_t aoff = ((m_base + (lane & 15)) * AST + (lane >> 4) * 8) * 2;
    const uint32_t boff = ((n_base + (lane >> 4) * 8 + (lane & 7)) * AST
                           + ((lane >> 3) & 1) * 8) * 2;

    float d[4][4][4];
#pragma unroll
    for (int i = 0; i < 4; i++)
#pragma unroll
        for (int j = 0; j < 4; j++)
#pragma unroll
            for (int c = 0; c < 4; c++) d[i][j][c] = 0.f;

    float4 xa[4]; uint2 wh4[4], wl4[4];

    auto load_chunk = [&](int kc) {
        const int k0 = kc * 32;
#pragma unroll
        for (int it = 0; it < 4; it++) {
            int idx = tid + it * 256;
            int r = idx >> 3, c4 = (idx & 7) * 4;
            int gr = row0 + r; if (gr >= M) gr = M - 1;
            xa[it]  = *(const float4*)(X + gr * DIMIN + k0 + c4);
            wh4[it] = *(const uint2*)(g_Wth + (col0 + r) * DIMIN + k0 + c4);
            wl4[it] = *(const uint2*)(g_Wtl + (col0 + r) * DIMIN + k0 + c4);
        }
    };
    auto store_stage = [&](int s) {
        char* st = smraw + s * STG;
#pragma unroll
        for (int it = 0; it < 4; it++) {
            int idx = tid + it * 256;
            int r = idx >> 3, c4 = (idx & 7) * 4;
            int off = (r * AST + c4) * 2;
            __nv_bfloat16 h0, l0, h1, l1, h2, l2, h3, l3;
            bsplit(xa[it].x, h0, l0); bsplit(xa[it].y, h1, l1);
            bsplit(xa[it].z, h2, l2); bsplit(xa[it].w, h3, l3);
            uint2 ah; ah.x = packbf2(h0, h1); ah.y = packbf2(h2, h3);
            uint2 al; al.x = packbf2(l0, l1); al.y = packbf2(l2, l3);
            *(uint2*)(st + off)             = ah;
            *(uint2*)(st + 10240 + off)     = al;
            *(uint2*)(st + 20480 + off)     = wh4[it];
            *(uint2*)(st + 30720 + off)     = wl4[it];
        }
    };

    load_chunk(0);
    store_stage(0);
    __syncthreads();

    for (int kc = 0; kc < 16; kc++) {
        const int cur = kc & 1;
        const bool more = (kc < 15);
        if (more) load_chunk(kc + 1);

        const uint32_t stg = sbase + cur * STG;
#pragma unroll
        for (int kk = 0; kk < 2; kk++) {
            const uint32_t kkb = kk * 32;
            unsigned bh[4][2], bl[4][2];
            ldmx4(bh[0][0], bh[0][1], bh[1][0], bh[1][1], stg + 20480 + boff + kkb);
            ldmx4(bh[2][0], bh[2][1], bh[3][0], bh[3][1], stg + 20480 + boff + kkb + 16 * AST * 2);
            ldmx4(bl[0][0], bl[0][1], bl[1][0], bl[1][1], stg + 30720 + boff + kkb);
            ldmx4(bl[2][0], bl[2][1], bl[3][0], bl[3][1], stg + 30720 + boff + kkb + 16 * AST * 2);
#pragma unroll
            for (int mi = 0; mi < 4; mi++) {
                unsigned a0, a1, a2, a3, l0, l1, l2, l3;
                ldmx4(a0, a1, a2, a3, stg + aoff + kkb + mi * 16 * AST * 2);
                ldmx4(l0, l1, l2, l3, stg + 10240 + aoff + kkb + mi * 16 * AST * 2);
#pragma unroll
                for (int ni = 0; ni < 4; ni++) {
                    mma_bf(d[mi][ni], a0, a1, a2, a3, bh[ni][0], bh[ni][1]);
                    mma_bf(d[mi][ni], a0, a1, a2, a3, bl[ni][0], bl[ni][1]);
                    mma_bf(d[mi][ni], l0, l1, l2, l3, bh[ni][0], bh[ni][1]);
                }
            }
        }
        if (more) {
            store_stage(cur ^ 1);
            __syncthreads();
        }
    }

    // epilogue: Q/K/V hi fp16; V also f32
    const int gid = lane >> 2, tq = lane & 3;
#pragma unroll
    for (int mi = 0; mi < 4; mi++) {
#pragma unroll
        for (int ni = 0; ni < 4; ni++) {
            int gc = col0 + n_base + ni * 8 + tq * 2;
            int which = gc >> 9;
            int hh = (gc >> 6) & 7;
            int dd = gc & 63;
            float sc = (which == 0) ? QK_SCALE : 1.f;
            __half* dh = (which == 0) ? g_Qh : (which == 1) ? g_Kh : g_Vh;
#pragma unroll
            for (int hrow = 0; hrow < 2; hrow++) {
                int m = row0 + m_base + mi * 16 + gid + hrow * 8;
                if (m >= M) continue;
                int bb = m / SEQ, pos = m % SEQ;
                int idx = ((bb * NH + hh) * SEQ + pos) * HD + dd;
                float f0 = d[mi][ni][hrow * 2 + 0] * sc;
                float f1 = d[mi][ni][hrow * 2 + 1] * sc;
                *(unsigned*)(dh + idx) = packh2(__float2half_rn(f0),
                                                __float2half_rn(f1));
                if (which == 2) {
                    float2 v; v.x = f0; v.y = f1;
                    *(float2*)(g_V + idx) = v;
                }
            }
        }
    }
}

// ---------------------------------------------------------------------------
// Fused attention on mma.sync, flash-style.
// Q,K,V: fp16 hi; P: fp16 hi. S = qh*kh ; O += ph*vh (1 MMA-set each)
// CTA = 128 threads (4 warps), q-tile 64, k-tile 64, 2-stage cp.async.
// ---------------------------------------------------------------------------
#define ATT_ST 72            // halves per smem row
#define T_ROW (64 * ATT_ST)  // 4608 halves per 64x64 tile
#define STG0_OFF T_ROW
#define STGSZ (2 * T_ROW)    // Kh | Vh

struct TileD { int kor; int vb; int nk; int mode; bool wrap; };
// mode: 0 = STATS (gene keys), 1 = inner-softmax probs, 2 = RAW

__device__ __forceinline__ TileD tdesc(bool is_img, int t) {
    TileD td;
    if (!is_img) {
        td.kor = t * 64;
        td.nk  = (SEQ - td.kor) < 64 ? (SEQ - td.kor) : 64;
        td.vb  = td.kor + NGENE;
        td.mode = 2; td.wrap = true;
    } else if (t < 16) {
        td.kor = NIMG + t * 64; td.nk = 64; td.vb = 0; td.mode = 0; td.wrap = false;
    } else if (t < 32) {
        td.kor = NIMG + (t - 16) * 64; td.nk = 64; td.vb = (t - 16) * 64;
        td.mode = 1; td.wrap = false;
    } else {
        td.kor = (t - 32) * 64;
        td.nk  = (NIMG - td.kor) < 64 ? (NIMG - td.kor) : 64;
        td.vb  = td.kor + NGENE;
        td.mode = 2; td.wrap = false;
    }
    return td;
}

__global__ __launch_bounds__(128)
void attn_mma(float* __restrict__ out)
{
    extern __shared__ __align__(16) __half smh[];
    const int tid = threadIdx.x;
    const int lane = tid & 31, wid = tid >> 5;
    const int tq = lane & 3;
    const int bh = blockIdx.x, qt = blockIdx.y;
    const int bhoff = bh * SEQ * HD;

    const bool is_img = (qt >= 16);
    int qorig0, tbase, nq;
    if (!is_img) { qorig0 = NIMG + qt * 64; tbase = qt * 64; nq = 64; }
    else {
        int i0 = (qt - 16) * 64;
        qorig0 = i0; tbase = NGENE + i0;
        nq = NIMG - i0; if (nq > 64) nq = 64;
    }
    const int ntiles = is_img ? 37 : 21;
    const uint32_t sb = smem_u32(smh);

    // ---- issue Q tile (Qh) via cp.async ----
#pragma unroll
    for (int i = 0; i < 4; i++) {
        int id = tid + i * 128;
        int row = id >> 3, c8 = (id & 7) * 8;
        int tok = qorig0 + (row < nq ? row : nq - 1);
        const __half* src = g_Qh + bhoff + tok * HD + c8;
        uint32_t dst = sb + (row * ATT_ST + c8) * 2;
        CP16(dst, src);
    }
    CP_COMMIT();

    auto issue_kv = [&](int t, int s) {
        TileD td = tdesc(is_img, t);
        uint32_t stg = sb + (STG0_OFF + s * STGSZ) * 2;
#pragma unroll
        for (int i = 0; i < 8; i++) {
            int id = tid + i * 128;
            int arr = id >> 9, rem = id & 511;   // 0 = Kh, 1 = Vh
            int row = rem >> 3, c8 = (rem & 7) * 8;
            int rc = row < td.nk ? row : td.nk - 1;
            const __half* src;
            if (arr == 0) {
                src = g_Kh + bhoff + (td.kor + rc) * HD + c8;
            } else {
                int vi = td.vb + rc;
                if (td.wrap && vi >= SEQ) vi -= SEQ;
                src = g_Vh + bhoff + vi * HD + c8;
            }
            uint32_t dst = stg + (arr * T_ROW + row * ATT_ST + c8) * 2;
            CP16(dst, src);
        }
        CP_COMMIT();
    };

    issue_kv(0, 0);
    CP_WAIT(1);            // Q done (stage0 may be in flight)
    __syncthreads();

    // ---- Q A-fragments (held in regs for the whole kernel) ----
    const int wm = wid;    // warp m-tile
    unsigned qa_h[4][4];
    {
        uint32_t aoff = sb + (((wm * 16 + (lane & 15)) * ATT_ST + (lane >> 4) * 8)) * 2;
#pragma unroll
        for (int c = 0; c < 4; c++)
            ldmx4(qa_h[c][0], qa_h[c][1], qa_h[c][2], qa_h[c][3], aoff + c * 32);
    }

    float O[8][4];
#pragma unroll
    for (int j = 0; j < 8; j++)
#pragma unroll
        for (int c = 0; c < 4; c++) O[j][c] = 0.f;
    float m0 = -INFINITY, m1 = -INFINITY, l0 = 0.f, l1 = 0.f;
    float mg0 = -INFINITY, mg1 = -INFINITY, lg0 = 0.f, lg1 = 0.f;
    float ivl0 = 0.f, ivl1 = 0.f;

    // per-lane ldmatrix address components
    const uint32_t krow = (lane >> 4) * 8 + (lane & 7);       // for K (n-rows)
    const uint32_t ksel = ((lane >> 3) & 1) * 8;              // k halves
    const uint32_t vrow = ((lane >> 3) & 1) * 8 + (lane & 7); // for V (k-rows)
    const uint32_t vcol = (lane >> 4) * 8;

    for (int t = 0; t < ntiles; t++) {
        const int cur = t & 1;
        const bool more = (t + 1 < ntiles);
        TileD td = tdesc(is_img, t);
        if (more) issue_kv(t + 1, cur ^ 1);
        if (more) CP_WAIT(1); else CP_WAIT(0);
        __syncthreads();

        const uint32_t stg = sb + (STG0_OFF + cur * STGSZ) * 2;

        // ---- S = Q K^T (1-term: qh*kh) ----
        float S[8][4];
#pragma unroll
        for (int j = 0; j < 8; j++)
#pragma unroll
            for (int c = 0; c < 4; c++) S[j][c] = 0.f;
#pragma unroll
        for (int jj = 0; jj < 4; jj++) {
            uint32_t rb = (jj * 16 + krow) * ATT_ST;
#pragma unroll
            for (int c = 0; c < 4; c++) {
                uint32_t ad = stg + ((rb + c * 16 + ksel)) * 2;
                unsigned b0, b1, b2, b3;
                ldmx4(b0, b1, b2, b3, ad);                    // Kh
                mma_f16(S[2*jj],   qa_h[c], b0, b1);
                mma_f16(S[2*jj+1], qa_h[c], b2, b3);
            }
        }

        if (td.mode == 0) {
            // inner-softmax stats over gene keys (rows: r0=lane>>2, r1=r0+8)
            float tm0 = -INFINITY, tm1 = -INFINITY;
#pragma unroll
            for (int j = 0; j < 8; j++) {
                tm0 = fmaxf(tm0, fmaxf(S[j][0], S[j][1]));
                tm1 = fmaxf(tm1, fmaxf(S[j][2], S[j][3]));
            }
            tm0 = fmaxf(tm0, __shfl_xor_sync(0xffffffffu, tm0, 1));
            tm0 = fmaxf(tm0, __shfl_xor_sync(0xffffffffu, tm0, 2));
            tm1 = fmaxf(tm1, __shfl_xor_sync(0xffffffffu, tm1, 1));
            tm1 = fmaxf(tm1, __shfl_xor_sync(0xffffffffu, tm1, 2));
            float mn0 = fmaxf(mg0, tm0), mn1 = fmaxf(mg1, tm1);
            float rs0 = 0.f, rs1 = 0.f;
#pragma unroll
            for (int j = 0; j < 8; j++) {
                rs0 += __expf(S[j][0] - mn0) + __expf(S[j][1] - mn0);
                rs1 += __expf(S[j][2] - mn1) + __expf(S[j][3] - mn1);
            }
            rs0 += __shfl_xor_sync(0xffffffffu, rs0, 1);
            rs0 += __shfl_xor_sync(0xffffffffu, rs0, 2);
            rs1 += __shfl_xor_sync(0xffffffffu, rs1, 1);
            rs1 += __shfl_xor_sync(0xffffffffu, rs1, 2);
            lg0 = lg0 * __expf(mg0 - mn0) + rs0; mg0 = mn0;
            lg1 = lg1 * __expf(mg1 - mn1) + rs1; mg1 = mn1;
        } else {
            if (is_img && t == 16) { ivl0 = 1.f / lg0; ivl1 = 1.f / lg1; }
            if (td.mode == 1) {
#pragma unroll
                for (int j = 0; j < 8; j++) {
                    S[j][0] = __expf(S[j][0] - mg0) * ivl0;
                    S[j][1] = __expf(S[j][1] - mg0) * ivl0;
                    S[j][2] = __expf(S[j][2] - mg1) * ivl1;
                    S[j][3] = __expf(S[j][3] - mg1) * ivl1;
                }
            } else if (td.nk < 64) {
#pragma unroll
                for (int j = 0; j < 8; j++) {
                    int c0 = j * 8 + tq * 2;
                    if (c0     >= td.nk) { S[j][0] = -INFINITY; S[j][2] = -INFINITY; }
                    if (c0 + 1 >= td.nk) { S[j][1] = -INFINITY; S[j][3] = -INFINITY; }
                }
            }
            // online softmax
            float tm0 = -INFINITY, tm1 = -INFINITY;
#pragma unroll
            for (int j = 0; j < 8; j++) {
                tm0 = fmaxf(tm0, fmaxf(S[j][0], S[j][1]));
                tm1 = fmaxf(tm1, fmaxf(S[j][2], S[j][3]));
            }
            tm0 = fmaxf(tm0, __shfl_xor_sync(0xffffffffu, tm0, 1));
            tm0 = fmaxf(tm0, __shfl_xor_sync(0xffffffffu, tm0, 2));
            tm1 = fmaxf(tm1, __shfl_xor_sync(0xffffffffu, tm1, 1));
            tm1 = fmaxf(tm1, __shfl_xor_sync(0xffffffffu, tm1, 2));
            float mn0 = fmaxf(m0, tm0), mn1 = fmaxf(m1, tm1);
            float sc0 = __expf(m0 - mn0), sc1 = __expf(m1 - mn1);
            float rs0 = 0.f, rs1 = 0.f;
#pragma unroll
            for (int j = 0; j < 8; j++) {
                S[j][0] = __expf(S[j][0] - mn0); rs0 += S[j][0];
                S[j][1] = __expf(S[j][1] - mn0); rs0 += S[j][1];
                S[j][2] = __expf(S[j][2] - mn1); rs1 += S[j][2];
                S[j][3] = __expf(S[j][3] - mn1); rs1 += S[j][3];
            }
            rs0 += __shfl_xor_sync(0xffffffffu, rs0, 1);
            rs0 += __shfl_xor_sync(0xffffffffu, rs0, 2);
            rs1 += __shfl_xor_sync(0xffffffffu, rs1, 1);
            rs1 += __shfl_xor_sync(0xffffffffu, rs1, 2);
            l0 = l0 * sc0 + rs0; m0 = mn0;
            l1 = l1 * sc1 + rs1; m1 = mn1;
#pragma unroll
            for (int j = 0; j < 8; j++) {
                O[j][0] *= sc0; O[j][1] *= sc0;
                O[j][2] *= sc1; O[j][3] *= sc1;
            }
            // P fragments (A, m16k16): hi only; emitted directly in
            // {a0,a1,a2,a3} = {(r0,k0),(r0+8,k0),(r0,k8),(r0+8,k8)} order.
            unsigned pha[4][4];
#pragma unroll
            for (int kk = 0; kk < 4; kk++) {
#pragma unroll
                for (int q = 0; q < 4; q++) {
                    int j = 2 * kk + (q >> 1);
                    int i0 = (q & 1) ? 2 : 0;
                    pha[kk][q] = packh2(__float2half_rn(S[j][i0]),
                                        __float2half_rn(S[j][i0 + 1]));
                }
            }
            // ---- O += P V (1-term: ph*vh) ----
#pragma unroll
            for (int kk = 0; kk < 4; kk++) {
                uint32_t rb = (kk * 16 + vrow) * ATT_ST + vcol;
#pragma unroll
                for (int dp = 0; dp < 4; dp++) {
                    uint32_t ad = stg + (T_ROW + rb + dp * 16) * 2;
                    unsigned v0, v1, v2, v3;
                    ldmx4t(v0, v1, v2, v3, ad);               // Vh
                    mma_f16(O[2*dp],   pha[kk], v0, v1);
                    mma_f16(O[2*dp+1], pha[kk], v2, v3);
                }
            }
        }
        __syncthreads();
    }

    // ---- epilogue ----
    const int bb = bh >> 3, hh = bh & 7;
    const int r0 = wm * 16 + (lane >> 2), r1 = r0 + 8;
    float inv0 = 1.f / l0, inv1 = 1.f / l1;
#pragma unroll
    for (int dj = 0; dj < 8; dj++) {
        int d0 = dj * 8 + tq * 2;
        if (r0 < nq) {
            float2 o; o.x = O[dj][0] * inv0; o.y = O[dj][1] * inv0;
            *(float2*)(out + ((long)(bb * SEQ + tbase + r0) * (NH * HD)) + hh * HD + d0) = o;
        }
        if (r1 < nq) {
            float2 o; o.x = O[dj][2] * inv1; o.y = O[dj][3] * inv1;
            *(float2*)(out + ((long)(bb * SEQ + tbase + r1) * (NH * HD)) + hh * HD + d0) = o;
        }
    }
}

// ---------------------------------------------------------------------------
// Kernel 3: depthwise conv residual, strips of 8
// ---------------------------------------------------------------------------
#define NSB 42

__global__ __launch_bounds__(256)
void resid_kernel(const float* __restrict__ wres, float* __restrict__ out)
{
    const int blk = blockIdx.x;
    const int sb = blk % NSB;
    const int bh = blk / NSB;
    const int bb = bh >> 3, hh = bh & 7;
    const int dd = threadIdx.x & 63;
    const int s = sb * 4 + (threadIdx.x >> 6);
    const int t0 = s * 8;
    if (t0 >= SEQ) return;

    const float* __restrict__ v = g_V + ((bb * NH + hh) * SEQ) * HD + dd;
    const float* __restrict__ w = wres + hh * KW;

    float win[40];
#pragma unroll
    for (int i = 0; i < 40; i++) {
        int p = t0 - KPAD + i;
        win[i] = (p >= 0 && p < SEQ) ? v[p * HD] : 0.f;
    }
    float o[8];
#pragma unroll
    for (int i = 0; i < 8; i++) o[i] = 0.f;
#pragma unroll
    for (int k = 0; k < KW; k++) {
        float wk = __ldg(w + k);
#pragma unroll
        for (int i = 0; i < 8; i++) o[i] += wk * win[i + k];
    }
#pragma unroll
    for (int i = 0; i < 8; i++) {
        int t = t0 + i;
        if (t < SEQ) {
            int oi = (bb * SEQ + t) * (NH * HD) + hh * HD + dd;
            out[oi] += o[i];
        }
    }
}

// ---------------------------------------------------------------------------
extern "C" void kernel_launch(void* const* d_in, const int* in_sizes, int n_in,
                              void* d_out, int out_size)
{
    const float* x     = (const float*)d_in[0];
    const float* w_qkv = (const float*)d_in[1];
    const float* w_res = (const float*)d_in[2];
    float* out = (float*)d_out;

    const int gemm_smem = 2 * STG;                            // 81920 B
    cudaFuncSetAttribute(qkv_gemm_mma, cudaFuncAttributeMaxDynamicSharedMemorySize, gemm_smem);
    const int attn_smem = (T_ROW + 2 * STGSZ) * 2;            // 46080 B
    cudaFuncSetAttribute(attn_mma, cudaFuncAttributeMaxDynamicSharedMemorySize, attn_smem);

    dim3 gp(NOUTC / 32, DIMIN / 32);
    prep_w_kernel<<<gp, dim3(32, 8)>>>(w_qkv);

    dim3 g1((BATCH * SEQ + 127) / 128, NOUTC / 128);
    qkv_gemm_mma<<<g1, 256, gemm_smem>>>(x);

    dim3 g2(BATCH * NH, 21);
    attn_mma<<<g2, 128, attn_smem>>>(out);

    resid_kernel<<<BATCH * NH * NSB, 256>>>(w_res, out);
}